// round 2
// baseline (speedup 1.0000x reference)
#include <cuda_runtime.h>
#include <cuda_bf16.h>

// Problem constants
#define TOK   8192
#define DM    2048
#define NH    16
#define DH    128
#define SEQ   1024
#define BSZ   256                       // page block size (tokens)
#define NBLK  64
#define CACHE_ELEMS (NBLK*2*NH*BSZ*DH)  // 33554432
#define OUT_ELEMS   (TOK*DM)            // 16777216

// Scratch (allocation-free: __device__ globals)
__device__ float g_Q [TOK*DM];
__device__ float g_K [TOK*DM];
__device__ float g_V [TOK*DM];
__device__ float g_AO[TOK*DM];

// ---------------------------------------------------------------------------
// SGEMM: C[M,N] = A[M,K] * B[N,K]^T   (both row-major, K contiguous)
// 128x128 tile, BK=16, 256 threads, 8x8 per thread.
// ---------------------------------------------------------------------------
__global__ void __launch_bounds__(256) sgemm_nt(const float* __restrict__ A,
                                                const float* __restrict__ B,
                                                float* __restrict__ C,
                                                int M, int N, int K)
{
    __shared__ float As[16][132];
    __shared__ float Bs[16][132];

    const int tid = threadIdx.x;
    const int bm  = blockIdx.y * 128;
    const int bn  = blockIdx.x * 128;
    const int tx  = tid & 15;
    const int ty  = tid >> 4;
    const int lr  = tid >> 2;        // 0..63
    const int lc  = (tid & 3) * 4;   // 0,4,8,12

    float acc[8][8];
    #pragma unroll
    for (int i = 0; i < 8; i++)
        #pragma unroll
        for (int j = 0; j < 8; j++) acc[i][j] = 0.0f;

    const float* Aptr = A + (size_t)(bm + lr) * K + lc;
    const float* Bptr = B + (size_t)(bn + lr) * K + lc;

    for (int k0 = 0; k0 < K; k0 += 16) {
        float4 a0 = *(const float4*)(Aptr + k0);
        float4 a1 = *(const float4*)(Aptr + (size_t)64 * K + k0);
        float4 b0 = *(const float4*)(Bptr + k0);
        float4 b1 = *(const float4*)(Bptr + (size_t)64 * K + k0);
        __syncthreads();
        As[lc+0][lr]    = a0.x; As[lc+1][lr]    = a0.y; As[lc+2][lr]    = a0.z; As[lc+3][lr]    = a0.w;
        As[lc+0][lr+64] = a1.x; As[lc+1][lr+64] = a1.y; As[lc+2][lr+64] = a1.z; As[lc+3][lr+64] = a1.w;
        Bs[lc+0][lr]    = b0.x; Bs[lc+1][lr]    = b0.y; Bs[lc+2][lr]    = b0.z; Bs[lc+3][lr]    = b0.w;
        Bs[lc+0][lr+64] = b1.x; Bs[lc+1][lr+64] = b1.y; Bs[lc+2][lr+64] = b1.z; Bs[lc+3][lr+64] = b1.w;
        __syncthreads();
        #pragma unroll
        for (int kk = 0; kk < 16; kk++) {
            float a[8], b[8];
            *(float4*)&a[0] = *(const float4*)&As[kk][ty * 8];
            *(float4*)&a[4] = *(const float4*)&As[kk][ty * 8 + 4];
            *(float4*)&b[0] = *(const float4*)&Bs[kk][tx * 8];
            *(float4*)&b[4] = *(const float4*)&Bs[kk][tx * 8 + 4];
            #pragma unroll
            for (int i = 0; i < 8; i++)
                #pragma unroll
                for (int j = 0; j < 8; j++)
                    acc[i][j] = fmaf(a[i], b[j], acc[i][j]);
        }
    }

    #pragma unroll
    for (int i = 0; i < 8; i++) {
        float* Crow = C + (size_t)(bm + ty * 8 + i) * N + bn + tx * 8;
        *(float4*)Crow       = make_float4(acc[i][0], acc[i][1], acc[i][2], acc[i][3]);
        *(float4*)(Crow + 4) = make_float4(acc[i][4], acc[i][5], acc[i][6], acc[i][7]);
    }
}

// ---------------------------------------------------------------------------
// RoPE (in-place on Q, K) + paged-KV scatter into the output cache region.
// One thread per (token, head, pair-index i in [0,64)).
// ---------------------------------------------------------------------------
__global__ void __launch_bounds__(256) rope_scatter(float* __restrict__ Q,
                                                    float* __restrict__ K,
                                                    const float* __restrict__ V,
                                                    const int* __restrict__ block_table,
                                                    float* __restrict__ cache)
{
    int idx = blockIdx.x * blockDim.x + threadIdx.x;  // TOK*NH*64
    int i = idx & 63;
    int h = (idx >> 6) & (NH - 1);
    int t = idx >> 10;
    if (t >= TOK) return;

    int pos = t & (SEQ - 1);
    float inv_freq = __powf(10000.0f, -(float)(2 * i) / 128.0f);
    float ang = (float)pos * inv_freq;
    float s, c;
    __sincosf(ang, &s, &c);

    size_t base = (size_t)t * DM + h * DH + i;
    float q1 = Q[base], q2 = Q[base + 64];
    Q[base]      = q1 * c - q2 * s;
    Q[base + 64] = q2 * c + q1 * s;

    float k1 = K[base], k2 = K[base + 64];
    float k1r = k1 * c - k2 * s;
    float k2r = k2 * c + k1 * s;
    K[base]      = k1r;
    K[base + 64] = k2r;

    int seq     = t >> 10;               // t / SEQ
    int logical = (t & (SEQ - 1)) >> 8;  // pos / BSZ
    int phys    = block_table[seq * (SEQ / BSZ) + logical];
    int off     = t & (BSZ - 1);         // pos % BSZ

    size_t kbase = (size_t)phys * (2 * NH * BSZ * DH) + (size_t)h * (BSZ * DH)
                 + (size_t)off * DH + i;
    cache[kbase]      = k1r;
    cache[kbase + 64] = k2r;
    size_t vbase = kbase + (size_t)NH * BSZ * DH;
    cache[vbase]      = V[base];
    cache[vbase + 64] = V[base + 64];
}

// ---------------------------------------------------------------------------
// Flash attention (causal, fp32). Block: 64 queries of one (b,h); 256 threads.
// K tiles of 64; online softmax; K/V share one smem buffer.
// ---------------------------------------------------------------------------
__global__ void __launch_bounds__(256) flash_attn(const float* __restrict__ Q,
                                                  const float* __restrict__ K,
                                                  const float* __restrict__ V,
                                                  float* __restrict__ O)
{
    extern __shared__ float sm[];
    float* Qs  = sm;                   // 64 x 128
    float* KVs = Qs + 64 * 128;        // 64 x 132 (padded)
    float* Ps  = KVs + 64 * 132;       // 64 x 65  (padded)

    const int qt   = blockIdx.x;       // 0..15
    const int bh   = blockIdx.y;       // 0..127
    const int b    = bh >> 4;
    const int h    = bh & 15;
    const int tid  = threadIdx.x;
    const int tx   = tid & 15;
    const int ty   = tid >> 4;
    const int warp = tid >> 5;
    const int lane = tid & 31;
    const int tok0 = b * SEQ;
    const int q0   = qt * 64;
    const float scale = 0.08838834764831845f; // 1/sqrt(128)

    // Load + scale Q tile
    #pragma unroll
    for (int r = 0; r < 8; r++) {
        int row = r * 8 + warp;
        float4 v = *(const float4*)&Q[(size_t)(tok0 + q0 + row) * DM + h * DH + lane * 4];
        v.x *= scale; v.y *= scale; v.z *= scale; v.w *= scale;
        *(float4*)&Qs[row * 128 + lane * 4] = v;
    }

    float m_i[4], l_i[4], acc[4][8];
    #pragma unroll
    for (int i = 0; i < 4; i++) {
        m_i[i] = -1e30f; l_i[i] = 0.0f;
        #pragma unroll
        for (int j = 0; j < 8; j++) acc[i][j] = 0.0f;
    }
    __syncthreads();

    for (int kt = 0; kt <= qt; kt++) {
        // Load K tile
        #pragma unroll
        for (int r = 0; r < 8; r++) {
            int row = r * 8 + warp;
            float4 v = *(const float4*)&K[(size_t)(tok0 + kt * 64 + row) * DM + h * DH + lane * 4];
            *(float4*)&KVs[row * 132 + lane * 4] = v;
        }
        __syncthreads();

        // Scores: 4x4 per thread (rows ty+16i, cols tx+16j)
        float s[4][4];
        #pragma unroll
        for (int i = 0; i < 4; i++)
            #pragma unroll
            for (int j = 0; j < 4; j++) s[i][j] = 0.0f;

        for (int d = 0; d < 128; d += 4) {
            float4 qv[4], kv[4];
            #pragma unroll
            for (int i = 0; i < 4; i++) qv[i] = *(const float4*)&Qs[(ty + 16 * i) * 128 + d];
            #pragma unroll
            for (int j = 0; j < 4; j++) kv[j] = *(const float4*)&KVs[(tx + 16 * j) * 132 + d];
            #pragma unroll
            for (int i = 0; i < 4; i++)
                #pragma unroll
                for (int j = 0; j < 4; j++) {
                    s[i][j] = fmaf(qv[i].x, kv[j].x, s[i][j]);
                    s[i][j] = fmaf(qv[i].y, kv[j].y, s[i][j]);
                    s[i][j] = fmaf(qv[i].z, kv[j].z, s[i][j]);
                    s[i][j] = fmaf(qv[i].w, kv[j].w, s[i][j]);
                }
        }

        if (kt == qt) {  // diagonal tile: causal mask
            #pragma unroll
            for (int i = 0; i < 4; i++)
                #pragma unroll
                for (int j = 0; j < 4; j++)
                    if (tx + 16 * j > ty + 16 * i) s[i][j] = -1e30f;
        }

        // Online softmax update (row groups of 16 lanes)
        #pragma unroll
        for (int i = 0; i < 4; i++) {
            float mloc = fmaxf(fmaxf(s[i][0], s[i][1]), fmaxf(s[i][2], s[i][3]));
            #pragma unroll
            for (int off = 8; off > 0; off >>= 1)
                mloc = fmaxf(mloc, __shfl_xor_sync(0xffffffffu, mloc, off));
            float mnew = fmaxf(m_i[i], mloc);
            float corr = __expf(m_i[i] - mnew);
            float lsum = 0.0f;
            #pragma unroll
            for (int j = 0; j < 4; j++) {
                float p = __expf(s[i][j] - mnew);
                Ps[(ty + 16 * i) * 65 + tx + 16 * j] = p;
                lsum += p;
            }
            #pragma unroll
            for (int off = 8; off > 0; off >>= 1)
                lsum += __shfl_xor_sync(0xffffffffu, lsum, off);
            l_i[i] = l_i[i] * corr + lsum;
            m_i[i] = mnew;
            #pragma unroll
            for (int j = 0; j < 8; j++) acc[i][j] *= corr;
        }
        __syncthreads();

        // Load V tile (reuse K buffer)
        #pragma unroll
        for (int r = 0; r < 8; r++) {
            int row = r * 8 + warp;
            float4 v = *(const float4*)&V[(size_t)(tok0 + kt * 64 + row) * DM + h * DH + lane * 4];
            *(float4*)&KVs[row * 132 + lane * 4] = v;
        }
        __syncthreads();

        // O += P * V   (thread owns rows ty+16i, dims tx*8..tx*8+7)
        for (int kc = 0; kc < 64; kc++) {
            float4 v0 = *(const float4*)&KVs[kc * 132 + tx * 8];
            float4 v1 = *(const float4*)&KVs[kc * 132 + tx * 8 + 4];
            #pragma unroll
            for (int i = 0; i < 4; i++) {
                float p = Ps[(ty + 16 * i) * 65 + kc];
                acc[i][0] = fmaf(p, v0.x, acc[i][0]);
                acc[i][1] = fmaf(p, v0.y, acc[i][1]);
                acc[i][2] = fmaf(p, v0.z, acc[i][2]);
                acc[i][3] = fmaf(p, v0.w, acc[i][3]);
                acc[i][4] = fmaf(p, v1.x, acc[i][4]);
                acc[i][5] = fmaf(p, v1.y, acc[i][5]);
                acc[i][6] = fmaf(p, v1.z, acc[i][6]);
                acc[i][7] = fmaf(p, v1.w, acc[i][7]);
            }
        }
        __syncthreads();
    }

    // Epilogue: normalize and store
    #pragma unroll
    for (int i = 0; i < 4; i++) {
        float inv_l = 1.0f / l_i[i];
        size_t row = (size_t)(tok0 + q0 + ty + 16 * i) * DM + h * DH + tx * 8;
        *(float4*)&O[row]     = make_float4(acc[i][0] * inv_l, acc[i][1] * inv_l,
                                            acc[i][2] * inv_l, acc[i][3] * inv_l);
        *(float4*)&O[row + 4] = make_float4(acc[i][4] * inv_l, acc[i][5] * inv_l,
                                            acc[i][6] * inv_l, acc[i][7] * inv_l);
    }
}

// ---------------------------------------------------------------------------
extern "C" void kernel_launch(void* const* d_in, const int* in_sizes, int n_in,
                              void* d_out, int out_size)
{
    const float* x   = (const float*)d_in[0];
    const float* Wq  = (const float*)d_in[1];
    const float* Wk  = (const float*)d_in[2];
    const float* Wv  = (const float*)d_in[3];
    const float* Wo  = (const float*)d_in[4];
    const float* kvc = (const float*)d_in[5];
    const int*   bt  = (const int*)d_in[7];

    float* out   = (float*)d_out;
    float* cache = out + OUT_ELEMS;

    float *Qb, *Kb, *Vb, *AOb;
    cudaGetSymbolAddress((void**)&Qb,  g_Q);
    cudaGetSymbolAddress((void**)&Kb,  g_K);
    cudaGetSymbolAddress((void**)&Vb,  g_V);
    cudaGetSymbolAddress((void**)&AOb, g_AO);

    dim3 gemm_grid(DM / 128, TOK / 128);  // (16, 64)

    sgemm_nt<<<gemm_grid, 256>>>(x, Wq, Qb, TOK, DM, DM);
    sgemm_nt<<<gemm_grid, 256>>>(x, Wk, Kb, TOK, DM, DM);
    sgemm_nt<<<gemm_grid, 256>>>(x, Wv, Vb, TOK, DM, DM);

    // new_cache = kv_cache (then overwritten for blocks holding this prefill)
    cudaMemcpyAsync(cache, kvc, (size_t)CACHE_ELEMS * sizeof(float),
                    cudaMemcpyDeviceToDevice);

    rope_scatter<<<(TOK * NH * 64) / 256, 256>>>(Qb, Kb, Vb, bt, cache);

    int smem_bytes = (64 * 128 + 64 * 132 + 64 * 65) * (int)sizeof(float); // 83200
    cudaFuncSetAttribute(flash_attn, cudaFuncAttributeMaxDynamicSharedMemorySize, smem_bytes);
    flash_attn<<<dim3(SEQ / 64, 8 * NH), 256, smem_bytes>>>(Qb, Kb, Vb, AOb);

    sgemm_nt<<<gemm_grid, 256>>>(AOb, Wo, out, TOK, DM, DM);
}

// round 7
// speedup vs baseline: 1.1188x; 1.1188x over previous
#include <cuda_runtime.h>
#include <cuda_bf16.h>
#include <cstdint>

// Problem constants
#define TOK   8192
#define DM    2048
#define NH    16
#define DH    128
#define SEQ   1024
#define BSZ   256
#define NBLK  64
#define CACHE_ELEMS (NBLK*2*NH*BSZ*DH)  // 33554432
#define OUT_ELEMS   (TOK*DM)            // 16777216

// Scratch
__device__ float g_Q [TOK*DM];
__device__ float g_K [TOK*DM];
__device__ float g_V [TOK*DM];
__device__ float g_AO[TOK*DM];

__device__ __forceinline__ uint32_t smem_u32(const void* p) {
    uint32_t a;
    asm("{ .reg .u64 t; cvta.to.shared.u64 t, %1; cvt.u32.u64 %0, t; }" : "=r"(a) : "l"(p));
    return a;
}

// ---------------------------------------------------------------------------
// 3xTF32 mma.sync GEMM:  C[M,N] = A[M,K] * B[N,K]^T  (row-major, K contiguous)
// CTA tile 128x128x32, 256 threads (8 warps = 2m x 4n), warp tile 64x32.
// cp.async double-buffered smem; operands split hi/lo tf32 for fp32-class
// accuracy (hi*hi + hi*lo + lo*hi).
// ---------------------------------------------------------------------------
#define GK 2048
#define BK 32
#define NSTEP (GK / BK)        // 64
#define PAD_STRIDE 36          // floats per row in smem
#define TILE_U (128 * PAD_STRIDE)
#define GEMM_SMEM (4 * TILE_U * 4)   // 73728 bytes

__device__ __forceinline__ void cp_async16(uint32_t dst, const void* src) {
    asm volatile("cp.async.ca.shared.global [%0], [%1], 16;" :: "r"(dst), "l"(src));
}
__device__ __forceinline__ void mma_tf32(float* d, const uint32_t* a, const uint32_t* b) {
    asm volatile(
        "mma.sync.aligned.m16n8k8.row.col.f32.tf32.tf32.f32 "
        "{%0,%1,%2,%3}, {%4,%5,%6,%7}, {%8,%9}, {%0,%1,%2,%3};"
        : "+f"(d[0]), "+f"(d[1]), "+f"(d[2]), "+f"(d[3])
        : "r"(a[0]), "r"(a[1]), "r"(a[2]), "r"(a[3]), "r"(b[0]), "r"(b[1]));
}
// Split x into hi (rna tf32) + lo (rna tf32 of residual)
__device__ __forceinline__ void split_tf32(uint32_t xb, uint32_t& hi, uint32_t& lo) {
    float x = __uint_as_float(xb);
    uint32_t h;
    asm("cvt.rna.tf32.f32 %0, %1;" : "=r"(h) : "f"(x));
    float l = x - __uint_as_float(h);
    uint32_t lt;
    asm("cvt.rna.tf32.f32 %0, %1;" : "=r"(lt) : "f"(l));
    hi = h; lo = lt;
}

__global__ void __launch_bounds__(256, 1) gemm_tf32x3(const float* __restrict__ A,
                                                      const float* __restrict__ B,
                                                      float* __restrict__ C)
{
    extern __shared__ uint32_t smu[];
    uint32_t* As[2] = { smu,            smu + TILE_U };
    uint32_t* Bs[2] = { smu + 2*TILE_U, smu + 3*TILE_U };
    const uint32_t as_addr[2] = { smem_u32(As[0]), smem_u32(As[1]) };
    const uint32_t bs_addr[2] = { smem_u32(Bs[0]), smem_u32(Bs[1]) };

    const int tid  = threadIdx.x;
    const int lane = tid & 31;
    const int wid  = tid >> 5;
    const int wm   = wid & 1;    // 64 rows each
    const int wn   = wid >> 1;   // 32 cols each
    const int bm   = blockIdx.y * 128;
    const int bn   = blockIdx.x * 128;

    const int ldr = tid >> 3;
    const int ldc = tid & 7;
    const float* Ag = A + (size_t)(bm + ldr) * GK + ldc * 4;
    const float* Bg = B + (size_t)(bn + ldr) * GK + ldc * 4;

    #define LOAD_TILES(KIDX, BUF) do {                                              \
        uint32_t _ad = as_addr[BUF] + (ldr * PAD_STRIDE + ldc * 4) * 4;             \
        uint32_t _bd = bs_addr[BUF] + (ldr * PAD_STRIDE + ldc * 4) * 4;             \
        const float* _as = Ag + (KIDX) * BK;                                        \
        const float* _bs = Bg + (KIDX) * BK;                                        \
        _Pragma("unroll")                                                           \
        for (int _i = 0; _i < 4; _i++) {                                            \
            cp_async16(_ad + _i * 32 * PAD_STRIDE * 4, _as + (size_t)_i * 32 * GK); \
            cp_async16(_bd + _i * 32 * PAD_STRIDE * 4, _bs + (size_t)_i * 32 * GK); \
        }                                                                           \
        asm volatile("cp.async.commit_group;");                                     \
    } while (0)

    float acc[4][4][4];
    #pragma unroll
    for (int mi = 0; mi < 4; mi++)
        #pragma unroll
        for (int nj = 0; nj < 4; nj++)
            #pragma unroll
            for (int r = 0; r < 4; r++) acc[mi][nj][r] = 0.0f;

    LOAD_TILES(0, 0);

    const int r0 = lane >> 2;
    const int c0 = lane & 3;

    for (int s = 0; s < NSTEP; s++) {
        const int buf = s & 1;
        if (s + 1 < NSTEP) {
            LOAD_TILES(s + 1, buf ^ 1);
            asm volatile("cp.async.wait_group 1;");
        } else {
            asm volatile("cp.async.wait_group 0;");
        }
        __syncthreads();

        const uint32_t* Asb = As[buf];
        const uint32_t* Bsb = Bs[buf];
        #pragma unroll
        for (int kk = 0; kk < 4; kk++) {
            const int kc = kk * 8 + c0;
            uint32_t ah[4][4], al[4][4], bh[4][2], bl[4][2];
            #pragma unroll
            for (int mi = 0; mi < 4; mi++) {
                const int row = wm * 64 + mi * 16 + r0;
                split_tf32(Asb[row * PAD_STRIDE + kc],           ah[mi][0], al[mi][0]);
                split_tf32(Asb[(row + 8) * PAD_STRIDE + kc],     ah[mi][1], al[mi][1]);
                split_tf32(Asb[row * PAD_STRIDE + kc + 4],       ah[mi][2], al[mi][2]);
                split_tf32(Asb[(row + 8) * PAD_STRIDE + kc + 4], ah[mi][3], al[mi][3]);
            }
            #pragma unroll
            for (int nj = 0; nj < 4; nj++) {
                const int n = wn * 32 + nj * 8 + r0;
                split_tf32(Bsb[n * PAD_STRIDE + kc],     bh[nj][0], bl[nj][0]);
                split_tf32(Bsb[n * PAD_STRIDE + kc + 4], bh[nj][1], bl[nj][1]);
            }
            #pragma unroll
            for (int mi = 0; mi < 4; mi++)
                #pragma unroll
                for (int nj = 0; nj < 4; nj++) {
                    mma_tf32(acc[mi][nj], ah[mi], bl[nj]);   // hi*lo
                    mma_tf32(acc[mi][nj], al[mi], bh[nj]);   // lo*hi
                    mma_tf32(acc[mi][nj], ah[mi], bh[nj]);   // hi*hi (last: biggest term)
                }
        }
        __syncthreads();
    }

    #pragma unroll
    for (int mi = 0; mi < 4; mi++) {
        const int grow = bm + wm * 64 + mi * 16 + r0;
        #pragma unroll
        for (int nj = 0; nj < 4; nj++) {
            const int gcol = bn + wn * 32 + nj * 8 + c0 * 2;
            *(float2*)&C[(size_t)grow * DM + gcol]       = make_float2(acc[mi][nj][0], acc[mi][nj][1]);
            *(float2*)&C[(size_t)(grow + 8) * DM + gcol] = make_float2(acc[mi][nj][2], acc[mi][nj][3]);
        }
    }
}

// ---------------------------------------------------------------------------
// RoPE + paged-KV scatter (DRAM-bound, 72us — unchanged)
// ---------------------------------------------------------------------------
__global__ void __launch_bounds__(256) rope_scatter(float* __restrict__ Q,
                                                    float* __restrict__ K,
                                                    const float* __restrict__ V,
                                                    const int* __restrict__ block_table,
                                                    float* __restrict__ cache)
{
    int idx = blockIdx.x * blockDim.x + threadIdx.x;
    int i = idx & 63;
    int h = (idx >> 6) & (NH - 1);
    int t = idx >> 10;
    if (t >= TOK) return;

    int pos = t & (SEQ - 1);
    float inv_freq = __powf(10000.0f, -(float)(2 * i) / 128.0f);
    float ang = (float)pos * inv_freq;
    float s, c;
    __sincosf(ang, &s, &c);

    size_t base = (size_t)t * DM + h * DH + i;
    float q1 = Q[base], q2 = Q[base + 64];
    Q[base]      = q1 * c - q2 * s;
    Q[base + 64] = q2 * c + q1 * s;

    float k1 = K[base], k2 = K[base + 64];
    float k1r = k1 * c - k2 * s;
    float k2r = k2 * c + k1 * s;
    K[base]      = k1r;
    K[base + 64] = k2r;

    int seq     = t >> 10;
    int logical = (t & (SEQ - 1)) >> 8;
    int phys    = block_table[seq * (SEQ / BSZ) + logical];
    int off     = t & (BSZ - 1);

    size_t kbase = (size_t)phys * (2 * NH * BSZ * DH) + (size_t)h * (BSZ * DH)
                 + (size_t)off * DH + i;
    cache[kbase]      = k1r;
    cache[kbase + 64] = k2r;
    size_t vbase = kbase + (size_t)NH * BSZ * DH;
    cache[vbase]      = V[base];
    cache[vbase + 64] = V[base + 64];
}

// ---------------------------------------------------------------------------
// Flash attention (causal, fp32) — unchanged from R2
// ---------------------------------------------------------------------------
__global__ void __launch_bounds__(256) flash_attn(const float* __restrict__ Q,
                                                  const float* __restrict__ K,
                                                  const float* __restrict__ V,
                                                  float* __restrict__ O)
{
    extern __shared__ float smf[];
    float* Qs  = smf;
    float* KVs = Qs + 64 * 128;
    float* Ps  = KVs + 64 * 132;

    const int qt   = blockIdx.x;
    const int bh   = blockIdx.y;
    const int b    = bh >> 4;
    const int h    = bh & 15;
    const int tid  = threadIdx.x;
    const int tx   = tid & 15;
    const int ty   = tid >> 4;
    const int warp = tid >> 5;
    const int lane = tid & 31;
    const int tok0 = b * SEQ;
    const int q0   = qt * 64;
    const float scale = 0.08838834764831845f;

    #pragma unroll
    for (int r = 0; r < 8; r++) {
        int row = r * 8 + warp;
        float4 v = *(const float4*)&Q[(size_t)(tok0 + q0 + row) * DM + h * DH + lane * 4];
        v.x *= scale; v.y *= scale; v.z *= scale; v.w *= scale;
        *(float4*)&Qs[row * 128 + lane * 4] = v;
    }

    float m_i[4], l_i[4], acc[4][8];
    #pragma unroll
    for (int i = 0; i < 4; i++) {
        m_i[i] = -1e30f; l_i[i] = 0.0f;
        #pragma unroll
        for (int j = 0; j < 8; j++) acc[i][j] = 0.0f;
    }
    __syncthreads();

    for (int kt = 0; kt <= qt; kt++) {
        #pragma unroll
        for (int r = 0; r < 8; r++) {
            int row = r * 8 + warp;
            float4 v = *(const float4*)&K[(size_t)(tok0 + kt * 64 + row) * DM + h * DH + lane * 4];
            *(float4*)&KVs[row * 132 + lane * 4] = v;
        }
        __syncthreads();

        float s[4][4];
        #pragma unroll
        for (int i = 0; i < 4; i++)
            #pragma unroll
            for (int j = 0; j < 4; j++) s[i][j] = 0.0f;

        for (int d = 0; d < 128; d += 4) {
            float4 qv[4], kv[4];
            #pragma unroll
            for (int i = 0; i < 4; i++) qv[i] = *(const float4*)&Qs[(ty + 16 * i) * 128 + d];
            #pragma unroll
            for (int j = 0; j < 4; j++) kv[j] = *(const float4*)&KVs[(tx + 16 * j) * 132 + d];
            #pragma unroll
            for (int i = 0; i < 4; i++)
                #pragma unroll
                for (int j = 0; j < 4; j++) {
                    s[i][j] = fmaf(qv[i].x, kv[j].x, s[i][j]);
                    s[i][j] = fmaf(qv[i].y, kv[j].y, s[i][j]);
                    s[i][j] = fmaf(qv[i].z, kv[j].z, s[i][j]);
                    s[i][j] = fmaf(qv[i].w, kv[j].w, s[i][j]);
                }
        }

        if (kt == qt) {
            #pragma unroll
            for (int i = 0; i < 4; i++)
                #pragma unroll
                for (int j = 0; j < 4; j++)
                    if (tx + 16 * j > ty + 16 * i) s[i][j] = -1e30f;
        }

        #pragma unroll
        for (int i = 0; i < 4; i++) {
            float mloc = fmaxf(fmaxf(s[i][0], s[i][1]), fmaxf(s[i][2], s[i][3]));
            #pragma unroll
            for (int off = 8; off > 0; off >>= 1)
                mloc = fmaxf(mloc, __shfl_xor_sync(0xffffffffu, mloc, off));
            float mnew = fmaxf(m_i[i], mloc);
            float corr = __expf(m_i[i] - mnew);
            float lsum = 0.0f;
            #pragma unroll
            for (int j = 0; j < 4; j++) {
                float p = __expf(s[i][j] - mnew);
                Ps[(ty + 16 * i) * 65 + tx + 16 * j] = p;
                lsum += p;
            }
            #pragma unroll
            for (int off = 8; off > 0; off >>= 1)
                lsum += __shfl_xor_sync(0xffffffffu, lsum, off);
            l_i[i] = l_i[i] * corr + lsum;
            m_i[i] = mnew;
            #pragma unroll
            for (int j = 0; j < 8; j++) acc[i][j] *= corr;
        }
        __syncthreads();

        #pragma unroll
        for (int r = 0; r < 8; r++) {
            int row = r * 8 + warp;
            float4 v = *(const float4*)&V[(size_t)(tok0 + kt * 64 + row) * DM + h * DH + lane * 4];
            *(float4*)&KVs[row * 132 + lane * 4] = v;
        }
        __syncthreads();

        for (int kc = 0; kc < 64; kc++) {
            float4 v0 = *(const float4*)&KVs[kc * 132 + tx * 8];
            float4 v1 = *(const float4*)&KVs[kc * 132 + tx * 8 + 4];
            #pragma unroll
            for (int i = 0; i < 4; i++) {
                float p = Ps[(ty + 16 * i) * 65 + kc];
                acc[i][0] = fmaf(p, v0.x, acc[i][0]);
                acc[i][1] = fmaf(p, v0.y, acc[i][1]);
                acc[i][2] = fmaf(p, v0.z, acc[i][2]);
                acc[i][3] = fmaf(p, v0.w, acc[i][3]);
                acc[i][4] = fmaf(p, v1.x, acc[i][4]);
                acc[i][5] = fmaf(p, v1.y, acc[i][5]);
                acc[i][6] = fmaf(p, v1.z, acc[i][6]);
                acc[i][7] = fmaf(p, v1.w, acc[i][7]);
            }
        }
        __syncthreads();
    }

    #pragma unroll
    for (int i = 0; i < 4; i++) {
        float inv_l = 1.0f / l_i[i];
        size_t row = (size_t)(tok0 + q0 + ty + 16 * i) * DM + h * DH + tx * 8;
        *(float4*)&O[row]     = make_float4(acc[i][0] * inv_l, acc[i][1] * inv_l,
                                            acc[i][2] * inv_l, acc[i][3] * inv_l);
        *(float4*)&O[row + 4] = make_float4(acc[i][4] * inv_l, acc[i][5] * inv_l,
                                            acc[i][6] * inv_l, acc[i][7] * inv_l);
    }
}

// ---------------------------------------------------------------------------
extern "C" void kernel_launch(void* const* d_in, const int* in_sizes, int n_in,
                              void* d_out, int out_size)
{
    const float* x   = (const float*)d_in[0];
    const float* Wq  = (const float*)d_in[1];
    const float* Wk  = (const float*)d_in[2];
    const float* Wv  = (const float*)d_in[3];
    const float* Wo  = (const float*)d_in[4];
    const float* kvc = (const float*)d_in[5];
    const int*   bt  = (const int*)d_in[7];

    float* out   = (float*)d_out;
    float* cache = out + OUT_ELEMS;

    float *Qb, *Kb, *Vb, *AOb;
    cudaGetSymbolAddress((void**)&Qb,  g_Q);
    cudaGetSymbolAddress((void**)&Kb,  g_K);
    cudaGetSymbolAddress((void**)&Vb,  g_V);
    cudaGetSymbolAddress((void**)&AOb, g_AO);

    cudaFuncSetAttribute(gemm_tf32x3, cudaFuncAttributeMaxDynamicSharedMemorySize, GEMM_SMEM);

    dim3 gg(DM / 128, TOK / 128);  // (16, 64)
    gemm_tf32x3<<<gg, 256, GEMM_SMEM>>>(x, Wq, Qb);
    gemm_tf32x3<<<gg, 256, GEMM_SMEM>>>(x, Wk, Kb);
    gemm_tf32x3<<<gg, 256, GEMM_SMEM>>>(x, Wv, Vb);

    cudaMemcpyAsync(cache, kvc, (size_t)CACHE_ELEMS * sizeof(float),
                    cudaMemcpyDeviceToDevice);

    rope_scatter<<<(TOK * NH * 64) / 256, 256>>>(Qb, Kb, Vb, bt, cache);

    int smem_bytes = (64 * 128 + 64 * 132 + 64 * 65) * (int)sizeof(float);
    cudaFuncSetAttribute(flash_attn, cudaFuncAttributeMaxDynamicSharedMemorySize, smem_bytes);
    flash_attn<<<dim3(SEQ / 64, 8 * NH), 256, smem_bytes>>>(Qb, Kb, Vb, AOb);

    gemm_tf32x3<<<gg, 256, GEMM_SMEM>>>(AOb, Wo, out);
}

// round 10
// speedup vs baseline: 1.2799x; 1.1440x over previous
#include <cuda_runtime.h>
#include <cuda_bf16.h>
#include <cstdint>

// Problem constants
#define TOK   8192
#define DM    2048
#define NH    16
#define DH    128
#define SEQ   1024
#define BSZ   256
#define NBLK  64
#define CACHE_ELEMS (NBLK*2*NH*BSZ*DH)  // 33554432
#define OUT_ELEMS   (TOK*DM)            // 16777216

// Scratch
__device__ float g_Q [TOK*DM];
__device__ float g_K [TOK*DM];
__device__ float g_V [TOK*DM];
__device__ float g_AO[TOK*DM];

__device__ __forceinline__ uint32_t smem_u32(const void* p) {
    uint32_t a;
    asm("{ .reg .u64 t; cvta.to.shared.u64 t, %1; cvt.u32.u64 %0, t; }" : "=r"(a) : "l"(p));
    return a;
}
__device__ __forceinline__ uint32_t tf32_bits(float x) {
    uint32_t r; asm("cvt.rna.tf32.f32 %0, %1;" : "=r"(r) : "f"(x)); return r;
}
__device__ __forceinline__ void cp_async16(uint32_t dst, const void* src) {
    asm volatile("cp.async.ca.shared.global [%0], [%1], 16;" :: "r"(dst), "l"(src));
}
// D += A * B^T fragment op; verified mapping:
//   a0=(r0,c0) a1=(r0+8,c0) a2=(r0,c0+4) a3=(r0+8,c0+4)
//   b0=(n=r0,k=c0) b1=(n=r0,k=c0+4)
//   d0=(r0,2c0) d1=(r0,2c0+1) d2=(r0+8,2c0) d3=(r0+8,2c0+1)
__device__ __forceinline__ void mma_tf32(float* d, const uint32_t* a, const uint32_t* b) {
    asm volatile(
        "mma.sync.aligned.m16n8k8.row.col.f32.tf32.tf32.f32 "
        "{%0,%1,%2,%3}, {%4,%5,%6,%7}, {%8,%9}, {%0,%1,%2,%3};"
        : "+f"(d[0]), "+f"(d[1]), "+f"(d[2]), "+f"(d[3])
        : "r"(a[0]), "r"(a[1]), "r"(a[2]), "r"(a[3]), "r"(b[0]), "r"(b[1]));
}
__device__ __forceinline__ void split_tf32(uint32_t xb, uint32_t& hi, uint32_t& lo) {
    float x = __uint_as_float(xb);
    uint32_t h;
    asm("cvt.rna.tf32.f32 %0, %1;" : "=r"(h) : "f"(x));
    float l = x - __uint_as_float(h);
    uint32_t lt;
    asm("cvt.rna.tf32.f32 %0, %1;" : "=r"(lt) : "f"(l));
    hi = h; lo = lt;
}

// ---------------------------------------------------------------------------
// 3xTF32 mma.sync GEMM, multi-output: grid.x selects (B,C) pair per 16 N-tiles.
// C[M,N] = A[M,K] * B[N,K]^T ; CTA 128x128x32, 256 thr, warp 64x32.
// ---------------------------------------------------------------------------
#define GK 2048
#define BK 32
#define NSTEP (GK / BK)
#define PAD_STRIDE 36
#define TILE_U (128 * PAD_STRIDE)
#define GEMM_SMEM (4 * TILE_U * 4)   // 73728 bytes

__global__ void __launch_bounds__(256, 1) gemm_tf32x3_multi(
    const float* __restrict__ A,
    const float* __restrict__ B0, const float* __restrict__ B1, const float* __restrict__ B2,
    float* __restrict__ C0, float* __restrict__ C1, float* __restrict__ C2)
{
    extern __shared__ uint32_t smu[];
    uint32_t* As[2] = { smu,            smu + TILE_U };
    uint32_t* Bs[2] = { smu + 2*TILE_U, smu + 3*TILE_U };
    const uint32_t as_addr[2] = { smem_u32(As[0]), smem_u32(As[1]) };
    const uint32_t bs_addr[2] = { smem_u32(Bs[0]), smem_u32(Bs[1]) };

    const int sel = blockIdx.x >> 4;
    const float* B = (sel == 0) ? B0 : (sel == 1) ? B1 : B2;
    float*       C = (sel == 0) ? C0 : (sel == 1) ? C1 : C2;

    const int tid  = threadIdx.x;
    const int lane = tid & 31;
    const int wid  = tid >> 5;
    const int wm   = wid & 1;
    const int wn   = wid >> 1;
    const int bm   = blockIdx.y * 128;
    const int bn   = (blockIdx.x & 15) * 128;

    const int ldr = tid >> 3;
    const int ldc = tid & 7;
    const float* Ag = A + (size_t)(bm + ldr) * GK + ldc * 4;
    const float* Bg = B + (size_t)(bn + ldr) * GK + ldc * 4;

    #define LOAD_TILES(KIDX, BUF) do {                                              \
        uint32_t _ad = as_addr[BUF] + (ldr * PAD_STRIDE + ldc * 4) * 4;             \
        uint32_t _bd = bs_addr[BUF] + (ldr * PAD_STRIDE + ldc * 4) * 4;             \
        const float* _as = Ag + (KIDX) * BK;                                        \
        const float* _bs = Bg + (KIDX) * BK;                                        \
        _Pragma("unroll")                                                           \
        for (int _i = 0; _i < 4; _i++) {                                            \
            cp_async16(_ad + _i * 32 * PAD_STRIDE * 4, _as + (size_t)_i * 32 * GK); \
            cp_async16(_bd + _i * 32 * PAD_STRIDE * 4, _bs + (size_t)_i * 32 * GK); \
        }                                                                           \
        asm volatile("cp.async.commit_group;");                                     \
    } while (0)

    float acc[4][4][4];
    #pragma unroll
    for (int mi = 0; mi < 4; mi++)
        #pragma unroll
        for (int nj = 0; nj < 4; nj++)
            #pragma unroll
            for (int r = 0; r < 4; r++) acc[mi][nj][r] = 0.0f;

    LOAD_TILES(0, 0);

    const int r0 = lane >> 2;
    const int c0 = lane & 3;

    for (int s = 0; s < NSTEP; s++) {
        const int buf = s & 1;
        if (s + 1 < NSTEP) {
            LOAD_TILES(s + 1, buf ^ 1);
            asm volatile("cp.async.wait_group 1;");
        } else {
            asm volatile("cp.async.wait_group 0;");
        }
        __syncthreads();

        const uint32_t* Asb = As[buf];
        const uint32_t* Bsb = Bs[buf];
        #pragma unroll
        for (int kk = 0; kk < 4; kk++) {
            const int kc = kk * 8 + c0;
            uint32_t ah[4][4], al[4][4], bh[4][2], bl[4][2];
            #pragma unroll
            for (int mi = 0; mi < 4; mi++) {
                const int row = wm * 64 + mi * 16 + r0;
                split_tf32(Asb[row * PAD_STRIDE + kc],           ah[mi][0], al[mi][0]);
                split_tf32(Asb[(row + 8) * PAD_STRIDE + kc],     ah[mi][1], al[mi][1]);
                split_tf32(Asb[row * PAD_STRIDE + kc + 4],       ah[mi][2], al[mi][2]);
                split_tf32(Asb[(row + 8) * PAD_STRIDE + kc + 4], ah[mi][3], al[mi][3]);
            }
            #pragma unroll
            for (int nj = 0; nj < 4; nj++) {
                const int n = wn * 32 + nj * 8 + r0;
                split_tf32(Bsb[n * PAD_STRIDE + kc],     bh[nj][0], bl[nj][0]);
                split_tf32(Bsb[n * PAD_STRIDE + kc + 4], bh[nj][1], bl[nj][1]);
            }
            #pragma unroll
            for (int mi = 0; mi < 4; mi++)
                #pragma unroll
                for (int nj = 0; nj < 4; nj++) {
                    mma_tf32(acc[mi][nj], ah[mi], bl[nj]);
                    mma_tf32(acc[mi][nj], al[mi], bh[nj]);
                    mma_tf32(acc[mi][nj], ah[mi], bh[nj]);
                }
        }
        __syncthreads();
    }

    #pragma unroll
    for (int mi = 0; mi < 4; mi++) {
        const int grow = bm + wm * 64 + mi * 16 + r0;
        #pragma unroll
        for (int nj = 0; nj < 4; nj++) {
            const int gcol = bn + wn * 32 + nj * 8 + c0 * 2;
            *(float2*)&C[(size_t)grow * DM + gcol]       = make_float2(acc[mi][nj][0], acc[mi][nj][1]);
            *(float2*)&C[(size_t)(grow + 8) * DM + gcol] = make_float2(acc[mi][nj][2], acc[mi][nj][3]);
        }
    }
}

// ---------------------------------------------------------------------------
// RoPE + paged-KV scatter (DRAM-bound at 70% — unchanged)
// ---------------------------------------------------------------------------
__global__ void __launch_bounds__(256) rope_scatter(float* __restrict__ Q,
                                                    float* __restrict__ K,
                                                    const float* __restrict__ V,
                                                    const int* __restrict__ block_table,
                                                    float* __restrict__ cache)
{
    int idx = blockIdx.x * blockDim.x + threadIdx.x;
    int i = idx & 63;
    int h = (idx >> 6) & (NH - 1);
    int t = idx >> 10;
    if (t >= TOK) return;

    int pos = t & (SEQ - 1);
    float inv_freq = __powf(10000.0f, -(float)(2 * i) / 128.0f);
    float ang = (float)pos * inv_freq;
    float s, c;
    __sincosf(ang, &s, &c);

    size_t base = (size_t)t * DM + h * DH + i;
    float q1 = Q[base], q2 = Q[base + 64];
    Q[base]      = q1 * c - q2 * s;
    Q[base + 64] = q2 * c + q1 * s;

    float k1 = K[base], k2 = K[base + 64];
    float k1r = k1 * c - k2 * s;
    float k2r = k2 * c + k1 * s;
    K[base]      = k1r;
    K[base + 64] = k2r;

    int seq     = t >> 10;
    int logical = (t & (SEQ - 1)) >> 8;
    int phys    = block_table[seq * (SEQ / BSZ) + logical];
    int off     = t & (BSZ - 1);

    size_t kbase = (size_t)phys * (2 * NH * BSZ * DH) + (size_t)h * (BSZ * DH)
                 + (size_t)off * DH + i;
    cache[kbase]      = k1r;
    cache[kbase + 64] = k2r;
    size_t vbase = kbase + (size_t)NH * BSZ * DH;
    cache[vbase]      = V[base];
    cache[vbase + 64] = V[base + 64];
}

// ---------------------------------------------------------------------------
// Flash attention on tf32 mma.sync. BM=128 queries/CTA, BN=64 keys/tile.
// 8 warps; warp w owns rows 16w..16w+15 -> warp-private softmax.
// ---------------------------------------------------------------------------
#define QS_STRIDE 132
#define KV_STRIDE 132
#define PS_STRIDE 68
#define ATT_SMEM ((128*QS_STRIDE + 64*KV_STRIDE + 64*KV_STRIDE + 128*PS_STRIDE) * 4) // 169984

__global__ void __launch_bounds__(256, 1) flash_attn_mma(const float* __restrict__ Q,
                                                         const float* __restrict__ K,
                                                         const float* __restrict__ V,
                                                         float* __restrict__ O)
{
    extern __shared__ uint32_t smu[];
    uint32_t* Qs = smu;                     // [128][132] tf32 (pre-scaled)
    uint32_t* Ks = Qs + 128 * QS_STRIDE;    // [64][132]  tf32
    uint32_t* Vs = Ks + 64 * KV_STRIDE;     // [64][132]  tf32
    uint32_t* Ps = Vs + 64 * KV_STRIDE;     // [128][68]  tf32

    const int qt   = blockIdx.x;    // 0..7  (128 rows each)
    const int bh   = blockIdx.y;    // 0..127
    const int b    = bh >> 4;
    const int h    = bh & 15;
    const int tid  = threadIdx.x;
    const int warp = tid >> 5;
    const int lane = tid & 31;
    const int r0   = lane >> 2;
    const int c0   = lane & 3;
    const int tok0 = b * SEQ;
    const float scale = 0.08838834764831845f; // 1/sqrt(128)

    // Load + scale + round Q tile: 128 rows x 32 float4
    for (int i = tid; i < 128 * 32; i += 256) {
        int row = i >> 5;
        int c4  = (i & 31) * 4;
        float4 v = *(const float4*)&Q[(size_t)(tok0 + qt * 128 + row) * DM + h * DH + c4];
        uint32_t* dst = &Qs[row * QS_STRIDE + c4];
        dst[0] = tf32_bits(v.x * scale);
        dst[1] = tf32_bits(v.y * scale);
        dst[2] = tf32_bits(v.z * scale);
        dst[3] = tf32_bits(v.w * scale);
    }

    float m0 = -1e30f, m1 = -1e30f, l0 = 0.0f, l1 = 0.0f;
    float acc[16][4];
    #pragma unroll
    for (int j = 0; j < 16; j++)
        #pragma unroll
        for (int r = 0; r < 4; r++) acc[j][r] = 0.0f;

    const int ktmax = 2 * qt + 1;
    for (int kt = 0; kt <= ktmax; kt++) {
        __syncthreads();   // previous iteration done with Ks/Vs (and Qs store on kt=0)
        for (int i = tid; i < 64 * 32; i += 256) {
            int row = i >> 5;
            int c4  = (i & 31) * 4;
            size_t g = (size_t)(tok0 + kt * 64 + row) * DM + h * DH + c4;
            float4 kv = *(const float4*)&K[g];
            float4 vv = *(const float4*)&V[g];
            uint32_t* kd = &Ks[row * KV_STRIDE + c4];
            kd[0] = tf32_bits(kv.x); kd[1] = tf32_bits(kv.y);
            kd[2] = tf32_bits(kv.z); kd[3] = tf32_bits(kv.w);
            uint32_t* vd = &Vs[row * KV_STRIDE + c4];
            vd[0] = tf32_bits(vv.x); vd[1] = tf32_bits(vv.y);
            vd[2] = tf32_bits(vv.z); vd[3] = tf32_bits(vv.w);
        }
        __syncthreads();

        // S = Q K^T : warp rows 16w.., 8 n-tiles of 8 cols, K=128 (16 k8-steps)
        float s[8][4];
        #pragma unroll
        for (int j = 0; j < 8; j++)
            #pragma unroll
            for (int r = 0; r < 4; r++) s[j][r] = 0.0f;

        #pragma unroll
        for (int kk = 0; kk < 16; kk++) {
            const int kc = kk * 8 + c0;
            uint32_t af[4];
            const int row = warp * 16 + r0;
            af[0] = Qs[row * QS_STRIDE + kc];
            af[1] = Qs[(row + 8) * QS_STRIDE + kc];
            af[2] = Qs[row * QS_STRIDE + kc + 4];
            af[3] = Qs[(row + 8) * QS_STRIDE + kc + 4];
            #pragma unroll
            for (int j = 0; j < 8; j++) {
                uint32_t bf[2];
                bf[0] = Ks[(j * 8 + r0) * KV_STRIDE + kc];
                bf[1] = Ks[(j * 8 + r0) * KV_STRIDE + kc + 4];
                mma_tf32(s[j], af, bf);
            }
        }

        // causal mask (only tiles at/past the diagonal region)
        if (kt >= 2 * qt) {
            const int grow0 = qt * 128 + warp * 16 + r0;
            #pragma unroll
            for (int j = 0; j < 8; j++) {
                const int gcol = kt * 64 + j * 8 + 2 * c0;
                if (gcol     > grow0)     s[j][0] = -1e30f;
                if (gcol + 1 > grow0)     s[j][1] = -1e30f;
                if (gcol     > grow0 + 8) s[j][2] = -1e30f;
                if (gcol + 1 > grow0 + 8) s[j][3] = -1e30f;
            }
        }

        // warp-private online softmax (rows r0 and r0+8; reduce over quad lanes)
        float mx0 = -1e30f, mx1 = -1e30f;
        #pragma unroll
        for (int j = 0; j < 8; j++) {
            mx0 = fmaxf(mx0, fmaxf(s[j][0], s[j][1]));
            mx1 = fmaxf(mx1, fmaxf(s[j][2], s[j][3]));
        }
        mx0 = fmaxf(mx0, __shfl_xor_sync(0xffffffffu, mx0, 1));
        mx0 = fmaxf(mx0, __shfl_xor_sync(0xffffffffu, mx0, 2));
        mx1 = fmaxf(mx1, __shfl_xor_sync(0xffffffffu, mx1, 1));
        mx1 = fmaxf(mx1, __shfl_xor_sync(0xffffffffu, mx1, 2));

        const float mn0 = fmaxf(m0, mx0);
        const float mn1 = fmaxf(m1, mx1);
        const float corr0 = __expf(m0 - mn0);
        const float corr1 = __expf(m1 - mn1);
        float ls0 = 0.0f, ls1 = 0.0f;
        const int prow0 = warp * 16 + r0;
        #pragma unroll
        for (int j = 0; j < 8; j++) {
            float p0 = __expf(s[j][0] - mn0);
            float p1 = __expf(s[j][1] - mn0);
            float p2 = __expf(s[j][2] - mn1);
            float p3 = __expf(s[j][3] - mn1);
            ls0 += p0 + p1;
            ls1 += p2 + p3;
            Ps[prow0 * PS_STRIDE + j * 8 + 2 * c0]           = tf32_bits(p0);
            Ps[prow0 * PS_STRIDE + j * 8 + 2 * c0 + 1]       = tf32_bits(p1);
            Ps[(prow0 + 8) * PS_STRIDE + j * 8 + 2 * c0]     = tf32_bits(p2);
            Ps[(prow0 + 8) * PS_STRIDE + j * 8 + 2 * c0 + 1] = tf32_bits(p3);
        }
        ls0 += __shfl_xor_sync(0xffffffffu, ls0, 1);
        ls0 += __shfl_xor_sync(0xffffffffu, ls0, 2);
        ls1 += __shfl_xor_sync(0xffffffffu, ls1, 1);
        ls1 += __shfl_xor_sync(0xffffffffu, ls1, 2);
        l0 = l0 * corr0 + ls0;  m0 = mn0;
        l1 = l1 * corr1 + ls1;  m1 = mn1;

        #pragma unroll
        for (int j = 0; j < 16; j++) {
            acc[j][0] *= corr0; acc[j][1] *= corr0;
            acc[j][2] *= corr1; acc[j][3] *= corr1;
        }
        __syncwarp();

        // O += P V : K=64 (8 k8-steps), 16 n-tiles over DH=128
        #pragma unroll
        for (int kk = 0; kk < 8; kk++) {
            const int kc = kk * 8 + c0;
            uint32_t af[4];
            af[0] = Ps[prow0 * PS_STRIDE + kc];
            af[1] = Ps[(prow0 + 8) * PS_STRIDE + kc];
            af[2] = Ps[prow0 * PS_STRIDE + kc + 4];
            af[3] = Ps[(prow0 + 8) * PS_STRIDE + kc + 4];
            #pragma unroll
            for (int j = 0; j < 16; j++) {
                uint32_t bf[2];
                bf[0] = Vs[kc * KV_STRIDE + j * 8 + r0];
                bf[1] = Vs[(kc + 4) * KV_STRIDE + j * 8 + r0];
                mma_tf32(acc[j], af, bf);
            }
        }
    }

    // epilogue
    const float inv0 = 1.0f / l0;
    const float inv1 = 1.0f / l1;
    const size_t row0 = (size_t)(tok0 + qt * 128 + warp * 16 + r0);
    #pragma unroll
    for (int j = 0; j < 16; j++) {
        const int col = h * DH + j * 8 + 2 * c0;
        *(float2*)&O[row0 * DM + col]       = make_float2(acc[j][0] * inv0, acc[j][1] * inv0);
        *(float2*)&O[(row0 + 8) * DM + col] = make_float2(acc[j][2] * inv1, acc[j][3] * inv1);
    }
}

// ---------------------------------------------------------------------------
extern "C" void kernel_launch(void* const* d_in, const int* in_sizes, int n_in,
                              void* d_out, int out_size)
{
    const float* x   = (const float*)d_in[0];
    const float* Wq  = (const float*)d_in[1];
    const float* Wk  = (const float*)d_in[2];
    const float* Wv  = (const float*)d_in[3];
    const float* Wo  = (const float*)d_in[4];
    const float* kvc = (const float*)d_in[5];
    const int*   bt  = (const int*)d_in[7];

    float* out   = (float*)d_out;
    float* cache = out + OUT_ELEMS;

    float *Qb, *Kb, *Vb, *AOb;
    cudaGetSymbolAddress((void**)&Qb,  g_Q);
    cudaGetSymbolAddress((void**)&Kb,  g_K);
    cudaGetSymbolAddress((void**)&Vb,  g_V);
    cudaGetSymbolAddress((void**)&AOb, g_AO);

    cudaFuncSetAttribute(gemm_tf32x3_multi, cudaFuncAttributeMaxDynamicSharedMemorySize, GEMM_SMEM);
    cudaFuncSetAttribute(flash_attn_mma, cudaFuncAttributeMaxDynamicSharedMemorySize, ATT_SMEM);

    // fused QKV: 48 N-tile groups x 64 M-tiles
    gemm_tf32x3_multi<<<dim3(48, 64), 256, GEMM_SMEM>>>(x, Wq, Wk, Wv, Qb, Kb, Vb);

    cudaMemcpyAsync(cache, kvc, (size_t)CACHE_ELEMS * sizeof(float),
                    cudaMemcpyDeviceToDevice);

    rope_scatter<<<(TOK * NH * 64) / 256, 256>>>(Qb, Kb, Vb, bt, cache);

    flash_attn_mma<<<dim3(SEQ / 128, 8 * NH), 256, ATT_SMEM>>>(Qb, Kb, Vb, AOb);

    gemm_tf32x3_multi<<<dim3(16, 64), 256, GEMM_SMEM>>>(AOb, Wo, Wo, Wo, out, out, out);
}

// round 13
// speedup vs baseline: 2.1906x; 1.7115x over previous
#include <cuda_runtime.h>
#include <cuda_bf16.h>
#include <cstdint>

// Problem constants
#define TOK   8192
#define DM    2048
#define NH    16
#define DH    128
#define SEQ   1024
#define BSZ   256
#define NBLK  64
#define CACHE_ELEMS (NBLK*2*NH*BSZ*DH)  // 33554432
#define OUT_ELEMS   (TOK*DM)            // 16777216

// Scratch (fp32 activations for rope/attention)
__device__ float g_Q [TOK*DM];
__device__ float g_K [TOK*DM];
__device__ float g_V [TOK*DM];
// bf16 hi/lo planes for GEMM operands
__device__ __nv_bfloat16 g_xh [TOK*DM], g_xl [TOK*DM];
__device__ __nv_bfloat16 g_AOh[TOK*DM], g_AOl[TOK*DM];
__device__ __nv_bfloat16 g_Wqh[DM*DM], g_Wql[DM*DM];
__device__ __nv_bfloat16 g_Wkh[DM*DM], g_Wkl[DM*DM];
__device__ __nv_bfloat16 g_Wvh[DM*DM], g_Wvl[DM*DM];
__device__ __nv_bfloat16 g_Woh[DM*DM], g_Wol[DM*DM];

__device__ __forceinline__ uint32_t smem_u32(const void* p) {
    uint32_t a;
    asm("{ .reg .u64 t; cvta.to.shared.u64 t, %1; cvt.u32.u64 %0, t; }" : "=r"(a) : "l"(p));
    return a;
}
__device__ __forceinline__ uint32_t tf32_bits(float x) {
    uint32_t r; asm("cvt.rna.tf32.f32 %0, %1;" : "=r"(r) : "f"(x)); return r;
}
__device__ __forceinline__ void cp_async16(uint32_t dst, const void* src) {
    asm volatile("cp.async.ca.shared.global [%0], [%1], 16;" :: "r"(dst), "l"(src));
}
// tf32 m16n8k8 (attention) — verified mapping
__device__ __forceinline__ void mma_tf32(float* d, const uint32_t* a, const uint32_t* b) {
    asm volatile(
        "mma.sync.aligned.m16n8k8.row.col.f32.tf32.tf32.f32 "
        "{%0,%1,%2,%3}, {%4,%5,%6,%7}, {%8,%9}, {%0,%1,%2,%3};"
        : "+f"(d[0]), "+f"(d[1]), "+f"(d[2]), "+f"(d[3])
        : "r"(a[0]), "r"(a[1]), "r"(a[2]), "r"(a[3]), "r"(b[0]), "r"(b[1]));
}
// bf16 m16n8k16 (GEMM). Fragment layout (thread = r0*4+c0):
//   a0=(r0, 2c0|2c0+1) a1=(r0+8, same) a2=(r0, 2c0+8|+9) a3=(r0+8, same)
//   b0=(n=r0, k=2c0|2c0+1) b1=(n=r0, k+8)
//   d: same as tf32 (d0,d1)=(r0,2c0|2c0+1), (d2,d3)=(r0+8, ...)
__device__ __forceinline__ void mma_bf16(float* d, const uint32_t* a, const uint32_t* b) {
    asm volatile(
        "mma.sync.aligned.m16n8k16.row.col.f32.bf16.bf16.f32 "
        "{%0,%1,%2,%3}, {%4,%5,%6,%7}, {%8,%9}, {%0,%1,%2,%3};"
        : "+f"(d[0]), "+f"(d[1]), "+f"(d[2]), "+f"(d[3])
        : "r"(a[0]), "r"(a[1]), "r"(a[2]), "r"(a[3]), "r"(b[0]), "r"(b[1]));
}
__device__ __forceinline__ uint32_t pack_bf2(float x, float y) {
    __nv_bfloat16 hx = __float2bfloat16_rn(x);
    __nv_bfloat16 hy = __float2bfloat16_rn(y);
    return (uint32_t)__bfloat16_as_ushort(hx) | ((uint32_t)__bfloat16_as_ushort(hy) << 16);
}

// ---------------------------------------------------------------------------
// Pack fp32 -> (hi, lo) bf16 planes. 4 elems/thread.
// ---------------------------------------------------------------------------
__global__ void __launch_bounds__(256) pack_split(const float* __restrict__ s,
                                                  __nv_bfloat16* __restrict__ h,
                                                  __nv_bfloat16* __restrict__ l,
                                                  int n4)
{
    int i = blockIdx.x * 256 + threadIdx.x;
    if (i >= n4) return;
    float4 v = ((const float4*)s)[i];
    __nv_bfloat16 h0 = __float2bfloat16_rn(v.x), h1 = __float2bfloat16_rn(v.y);
    __nv_bfloat16 h2 = __float2bfloat16_rn(v.z), h3 = __float2bfloat16_rn(v.w);
    float r0 = v.x - __bfloat162float(h0), r1 = v.y - __bfloat162float(h1);
    float r2 = v.z - __bfloat162float(h2), r3 = v.w - __bfloat162float(h3);
    uint32_t hA = (uint32_t)__bfloat16_as_ushort(h0) | ((uint32_t)__bfloat16_as_ushort(h1) << 16);
    uint32_t hB = (uint32_t)__bfloat16_as_ushort(h2) | ((uint32_t)__bfloat16_as_ushort(h3) << 16);
    *(uint2*)&h[4 * (size_t)i] = make_uint2(hA, hB);
    *(uint2*)&l[4 * (size_t)i] = make_uint2(pack_bf2(r0, r1), pack_bf2(r2, r3));
}

// ---------------------------------------------------------------------------
// bf16 2-split GEMM: C[M,N] = A*B^T with A=Ah+Al, B=Bh+Bl.
// CTA 128x128x32, 256 thr (8 warps = 2m x 4n), warp 64x32.
// smem: per stage 4 planes (Ah,Al,Bh,Bl) 128 rows x 40 bf16 (80B) = 10240B each.
// Fragment LDS: u32 index row*20 + kk*8 + c0 (+4 for k+8, +160 for row+8) — bank-clean.
// ---------------------------------------------------------------------------
#define GK 2048
#define BBK 32
#define GNSTEP (GK / BBK)   // 64
#define PLANE_B 10240
#define STAGE_B (4 * PLANE_B)       // 40960
#define GEMM_SMEM (2 * STAGE_B)     // 81920

__global__ void __launch_bounds__(256, 1) gemm_bf16x3_multi(
    const __nv_bfloat16* __restrict__ Ah, const __nv_bfloat16* __restrict__ Al,
    const __nv_bfloat16* __restrict__ B0h, const __nv_bfloat16* __restrict__ B0l,
    const __nv_bfloat16* __restrict__ B1h, const __nv_bfloat16* __restrict__ B1l,
    const __nv_bfloat16* __restrict__ B2h, const __nv_bfloat16* __restrict__ B2l,
    float* __restrict__ C0, float* __restrict__ C1, float* __restrict__ C2)
{
    extern __shared__ uint32_t smu[];
    const uint32_t sbase = smem_u32(smu);

    const int sel = blockIdx.x >> 4;
    const __nv_bfloat16* Bh = (sel == 0) ? B0h : (sel == 1) ? B1h : B2h;
    const __nv_bfloat16* Bl = (sel == 0) ? B0l : (sel == 1) ? B1l : B2l;
    float*               C  = (sel == 0) ? C0  : (sel == 1) ? C1  : C2;

    const int tid  = threadIdx.x;
    const int lane = tid & 31;
    const int wid  = tid >> 5;
    const int wm   = wid & 1;
    const int wn   = wid >> 1;
    const int bm   = blockIdx.y * 128;
    const int bn   = (blockIdx.x & 15) * 128;
    const int r0   = lane >> 2;
    const int c0   = lane & 3;

    // cp.async mapping: per plane, thread covers rows (tid>>2) and +64; 16B chunk tid&3
    const int ldrow = tid >> 2;
    const int ldch  = tid & 3;
    const __nv_bfloat16* Ah_t = Ah + (size_t)(bm + ldrow) * GK + ldch * 8;
    const __nv_bfloat16* Al_t = Al + (size_t)(bm + ldrow) * GK + ldch * 8;
    const __nv_bfloat16* Bh_t = Bh + (size_t)(bn + ldrow) * GK + ldch * 8;
    const __nv_bfloat16* Bl_t = Bl + (size_t)(bn + ldrow) * GK + ldch * 8;
    const uint32_t sdst = sbase + ldrow * 80 + ldch * 16;

    #define LOAD_TILES(KIDX, BUF) do {                                           \
        const int _k0 = (KIDX) * BBK;                                            \
        const uint32_t _d = sdst + (BUF) * STAGE_B;                              \
        _Pragma("unroll")                                                        \
        for (int _i = 0; _i < 2; _i++) {                                         \
            const size_t _g = (size_t)_i * 64 * GK + _k0;                        \
            const uint32_t _o = _i * 64 * 80;                                    \
            cp_async16(_d + _o,               Ah_t + _g);                        \
            cp_async16(_d + _o + PLANE_B,     Al_t + _g);                        \
            cp_async16(_d + _o + 2*PLANE_B,   Bh_t + _g);                        \
            cp_async16(_d + _o + 3*PLANE_B,   Bl_t + _g);                        \
        }                                                                        \
        asm volatile("cp.async.commit_group;");                                  \
    } while (0)

    float acc[4][4][4];
    #pragma unroll
    for (int mi = 0; mi < 4; mi++)
        #pragma unroll
        for (int nj = 0; nj < 4; nj++)
            #pragma unroll
            for (int r = 0; r < 4; r++) acc[mi][nj][r] = 0.0f;

    LOAD_TILES(0, 0);

    for (int s = 0; s < GNSTEP; s++) {
        const int buf = s & 1;
        if (s + 1 < GNSTEP) {
            LOAD_TILES(s + 1, buf ^ 1);
            asm volatile("cp.async.wait_group 1;");
        } else {
            asm volatile("cp.async.wait_group 0;");
        }
        __syncthreads();

        const uint32_t* P   = smu + buf * (STAGE_B / 4);
        const uint32_t* PAh = P;
        const uint32_t* PAl = P + PLANE_B / 4;
        const uint32_t* PBh = P + 2 * PLANE_B / 4;
        const uint32_t* PBl = P + 3 * PLANE_B / 4;

        #pragma unroll
        for (int kk = 0; kk < 2; kk++) {
            uint32_t ah[4][4], al[4][4], bh[4][2], bl[4][2];
            #pragma unroll
            for (int mi = 0; mi < 4; mi++) {
                const int idx = (wm * 64 + mi * 16 + r0) * 20 + kk * 8 + c0;
                ah[mi][0] = PAh[idx];       ah[mi][1] = PAh[idx + 160];
                ah[mi][2] = PAh[idx + 4];   ah[mi][3] = PAh[idx + 164];
                al[mi][0] = PAl[idx];       al[mi][1] = PAl[idx + 160];
                al[mi][2] = PAl[idx + 4];   al[mi][3] = PAl[idx + 164];
            }
            #pragma unroll
            for (int nj = 0; nj < 4; nj++) {
                const int nidx = (wn * 32 + nj * 8 + r0) * 20 + kk * 8 + c0;
                bh[nj][0] = PBh[nidx];      bh[nj][1] = PBh[nidx + 4];
                bl[nj][0] = PBl[nidx];      bl[nj][1] = PBl[nidx + 4];
            }
            #pragma unroll
            for (int mi = 0; mi < 4; mi++)
                #pragma unroll
                for (int nj = 0; nj < 4; nj++) {
                    mma_bf16(acc[mi][nj], ah[mi], bl[nj]);
                    mma_bf16(acc[mi][nj], al[mi], bh[nj]);
                    mma_bf16(acc[mi][nj], ah[mi], bh[nj]);
                }
        }
        __syncthreads();
    }

    #pragma unroll
    for (int mi = 0; mi < 4; mi++) {
        const int grow = bm + wm * 64 + mi * 16 + r0;
        #pragma unroll
        for (int nj = 0; nj < 4; nj++) {
            const int gcol = bn + wn * 32 + nj * 8 + c0 * 2;
            *(float2*)&C[(size_t)grow * DM + gcol]       = make_float2(acc[mi][nj][0], acc[mi][nj][1]);
            *(float2*)&C[(size_t)(grow + 8) * DM + gcol] = make_float2(acc[mi][nj][2], acc[mi][nj][3]);
        }
    }
}

// ---------------------------------------------------------------------------
// RoPE + paged-KV scatter (DRAM-bound — unchanged)
// ---------------------------------------------------------------------------
__global__ void __launch_bounds__(256) rope_scatter(float* __restrict__ Q,
                                                    float* __restrict__ K,
                                                    const float* __restrict__ V,
                                                    const int* __restrict__ block_table,
                                                    float* __restrict__ cache)
{
    int idx = blockIdx.x * blockDim.x + threadIdx.x;
    int i = idx & 63;
    int h = (idx >> 6) & (NH - 1);
    int t = idx >> 10;
    if (t >= TOK) return;

    int pos = t & (SEQ - 1);
    float inv_freq = __powf(10000.0f, -(float)(2 * i) / 128.0f);
    float ang = (float)pos * inv_freq;
    float s, c;
    __sincosf(ang, &s, &c);

    size_t base = (size_t)t * DM + h * DH + i;
    float q1 = Q[base], q2 = Q[base + 64];
    Q[base]      = q1 * c - q2 * s;
    Q[base + 64] = q2 * c + q1 * s;

    float k1 = K[base], k2 = K[base + 64];
    float k1r = k1 * c - k2 * s;
    float k2r = k2 * c + k1 * s;
    K[base]      = k1r;
    K[base + 64] = k2r;

    int seq     = t >> 10;
    int logical = (t & (SEQ - 1)) >> 8;
    int phys    = block_table[seq * (SEQ / BSZ) + logical];
    int off     = t & (BSZ - 1);

    size_t kbase = (size_t)phys * (2 * NH * BSZ * DH) + (size_t)h * (BSZ * DH)
                 + (size_t)off * DH + i;
    cache[kbase]      = k1r;
    cache[kbase + 64] = k2r;
    size_t vbase = kbase + (size_t)NH * BSZ * DH;
    cache[vbase]      = V[base];
    cache[vbase + 64] = V[base + 64];
}

// ---------------------------------------------------------------------------
// Flash attention on tf32 mma.sync (verified R10). Epilogue now writes
// AO as bf16 hi/lo planes for the O-GEMM.
// ---------------------------------------------------------------------------
#define QS_STRIDE 132
#define KV_STRIDE 132
#define PS_STRIDE 68
#define ATT_SMEM ((128*QS_STRIDE + 64*KV_STRIDE + 64*KV_STRIDE + 128*PS_STRIDE) * 4)

__global__ void __launch_bounds__(256, 1) flash_attn_mma(const float* __restrict__ Q,
                                                         const float* __restrict__ K,
                                                         const float* __restrict__ V,
                                                         __nv_bfloat16* __restrict__ Oh,
                                                         __nv_bfloat16* __restrict__ Ol)
{
    extern __shared__ uint32_t smu[];
    uint32_t* Qs = smu;
    uint32_t* Ks = Qs + 128 * QS_STRIDE;
    uint32_t* Vs = Ks + 64 * KV_STRIDE;
    uint32_t* Ps = Vs + 64 * KV_STRIDE;

    const int qt   = blockIdx.x;
    const int bh   = blockIdx.y;
    const int b    = bh >> 4;
    const int h    = bh & 15;
    const int tid  = threadIdx.x;
    const int warp = tid >> 5;
    const int lane = tid & 31;
    const int r0   = lane >> 2;
    const int c0   = lane & 3;
    const int tok0 = b * SEQ;
    const float scale = 0.08838834764831845f;

    for (int i = tid; i < 128 * 32; i += 256) {
        int row = i >> 5;
        int c4  = (i & 31) * 4;
        float4 v = *(const float4*)&Q[(size_t)(tok0 + qt * 128 + row) * DM + h * DH + c4];
        uint32_t* dst = &Qs[row * QS_STRIDE + c4];
        dst[0] = tf32_bits(v.x * scale);
        dst[1] = tf32_bits(v.y * scale);
        dst[2] = tf32_bits(v.z * scale);
        dst[3] = tf32_bits(v.w * scale);
    }

    float m0 = -1e30f, m1 = -1e30f, l0 = 0.0f, l1 = 0.0f;
    float acc[16][4];
    #pragma unroll
    for (int j = 0; j < 16; j++)
        #pragma unroll
        for (int r = 0; r < 4; r++) acc[j][r] = 0.0f;

    const int ktmax = 2 * qt + 1;
    for (int kt = 0; kt <= ktmax; kt++) {
        __syncthreads();
        for (int i = tid; i < 64 * 32; i += 256) {
            int row = i >> 5;
            int c4  = (i & 31) * 4;
            size_t g = (size_t)(tok0 + kt * 64 + row) * DM + h * DH + c4;
            float4 kv = *(const float4*)&K[g];
            float4 vv = *(const float4*)&V[g];
            uint32_t* kd = &Ks[row * KV_STRIDE + c4];
            kd[0] = tf32_bits(kv.x); kd[1] = tf32_bits(kv.y);
            kd[2] = tf32_bits(kv.z); kd[3] = tf32_bits(kv.w);
            uint32_t* vd = &Vs[row * KV_STRIDE + c4];
            vd[0] = tf32_bits(vv.x); vd[1] = tf32_bits(vv.y);
            vd[2] = tf32_bits(vv.z); vd[3] = tf32_bits(vv.w);
        }
        __syncthreads();

        float s[8][4];
        #pragma unroll
        for (int j = 0; j < 8; j++)
            #pragma unroll
            for (int r = 0; r < 4; r++) s[j][r] = 0.0f;

        #pragma unroll
        for (int kk = 0; kk < 16; kk++) {
            const int kc = kk * 8 + c0;
            uint32_t af[4];
            const int row = warp * 16 + r0;
            af[0] = Qs[row * QS_STRIDE + kc];
            af[1] = Qs[(row + 8) * QS_STRIDE + kc];
            af[2] = Qs[row * QS_STRIDE + kc + 4];
            af[3] = Qs[(row + 8) * QS_STRIDE + kc + 4];
            #pragma unroll
            for (int j = 0; j < 8; j++) {
                uint32_t bf[2];
                bf[0] = Ks[(j * 8 + r0) * KV_STRIDE + kc];
                bf[1] = Ks[(j * 8 + r0) * KV_STRIDE + kc + 4];
                mma_tf32(s[j], af, bf);
            }
        }

        if (kt >= 2 * qt) {
            const int grow0 = qt * 128 + warp * 16 + r0;
            #pragma unroll
            for (int j = 0; j < 8; j++) {
                const int gcol = kt * 64 + j * 8 + 2 * c0;
                if (gcol     > grow0)     s[j][0] = -1e30f;
                if (gcol + 1 > grow0)     s[j][1] = -1e30f;
                if (gcol     > grow0 + 8) s[j][2] = -1e30f;
                if (gcol + 1 > grow0 + 8) s[j][3] = -1e30f;
            }
        }

        float mx0 = -1e30f, mx1 = -1e30f;
        #pragma unroll
        for (int j = 0; j < 8; j++) {
            mx0 = fmaxf(mx0, fmaxf(s[j][0], s[j][1]));
            mx1 = fmaxf(mx1, fmaxf(s[j][2], s[j][3]));
        }
        mx0 = fmaxf(mx0, __shfl_xor_sync(0xffffffffu, mx0, 1));
        mx0 = fmaxf(mx0, __shfl_xor_sync(0xffffffffu, mx0, 2));
        mx1 = fmaxf(mx1, __shfl_xor_sync(0xffffffffu, mx1, 1));
        mx1 = fmaxf(mx1, __shfl_xor_sync(0xffffffffu, mx1, 2));

        const float mn0 = fmaxf(m0, mx0);
        const float mn1 = fmaxf(m1, mx1);
        const float corr0 = __expf(m0 - mn0);
        const float corr1 = __expf(m1 - mn1);
        float ls0 = 0.0f, ls1 = 0.0f;
        const int prow0 = warp * 16 + r0;
        #pragma unroll
        for (int j = 0; j < 8; j++) {
            float p0 = __expf(s[j][0] - mn0);
            float p1 = __expf(s[j][1] - mn0);
            float p2 = __expf(s[j][2] - mn1);
            float p3 = __expf(s[j][3] - mn1);
            ls0 += p0 + p1;
            ls1 += p2 + p3;
            Ps[prow0 * PS_STRIDE + j * 8 + 2 * c0]           = tf32_bits(p0);
            Ps[prow0 * PS_STRIDE + j * 8 + 2 * c0 + 1]       = tf32_bits(p1);
            Ps[(prow0 + 8) * PS_STRIDE + j * 8 + 2 * c0]     = tf32_bits(p2);
            Ps[(prow0 + 8) * PS_STRIDE + j * 8 + 2 * c0 + 1] = tf32_bits(p3);
        }
        ls0 += __shfl_xor_sync(0xffffffffu, ls0, 1);
        ls0 += __shfl_xor_sync(0xffffffffu, ls0, 2);
        ls1 += __shfl_xor_sync(0xffffffffu, ls1, 1);
        ls1 += __shfl_xor_sync(0xffffffffu, ls1, 2);
        l0 = l0 * corr0 + ls0;  m0 = mn0;
        l1 = l1 * corr1 + ls1;  m1 = mn1;

        #pragma unroll
        for (int j = 0; j < 16; j++) {
            acc[j][0] *= corr0; acc[j][1] *= corr0;
            acc[j][2] *= corr1; acc[j][3] *= corr1;
        }
        __syncwarp();

        #pragma unroll
        for (int kk = 0; kk < 8; kk++) {
            const int kc = kk * 8 + c0;
            uint32_t af[4];
            af[0] = Ps[prow0 * PS_STRIDE + kc];
            af[1] = Ps[(prow0 + 8) * PS_STRIDE + kc];
            af[2] = Ps[prow0 * PS_STRIDE + kc + 4];
            af[3] = Ps[(prow0 + 8) * PS_STRIDE + kc + 4];
            #pragma unroll
            for (int j = 0; j < 16; j++) {
                uint32_t bf[2];
                bf[0] = Vs[kc * KV_STRIDE + j * 8 + r0];
                bf[1] = Vs[(kc + 4) * KV_STRIDE + j * 8 + r0];
                mma_tf32(acc[j], af, bf);
            }
        }
    }

    // epilogue: normalize, split to bf16 hi/lo planes
    const float inv0 = 1.0f / l0;
    const float inv1 = 1.0f / l1;
    const size_t row0 = (size_t)(tok0 + qt * 128 + warp * 16 + r0);
    #pragma unroll
    for (int j = 0; j < 16; j++) {
        const int col = h * DH + j * 8 + 2 * c0;
        float o0 = acc[j][0] * inv0, o1 = acc[j][1] * inv0;
        float o2 = acc[j][2] * inv1, o3 = acc[j][3] * inv1;
        __nv_bfloat16 h0 = __float2bfloat16_rn(o0), h1 = __float2bfloat16_rn(o1);
        __nv_bfloat16 h2 = __float2bfloat16_rn(o2), h3 = __float2bfloat16_rn(o3);
        size_t off0 = row0 * DM + col;
        size_t off1 = (row0 + 8) * DM + col;
        *(uint32_t*)&Oh[off0] = (uint32_t)__bfloat16_as_ushort(h0) | ((uint32_t)__bfloat16_as_ushort(h1) << 16);
        *(uint32_t*)&Oh[off1] = (uint32_t)__bfloat16_as_ushort(h2) | ((uint32_t)__bfloat16_as_ushort(h3) << 16);
        *(uint32_t*)&Ol[off0] = pack_bf2(o0 - __bfloat162float(h0), o1 - __bfloat162float(h1));
        *(uint32_t*)&Ol[off1] = pack_bf2(o2 - __bfloat162float(h2), o3 - __bfloat162float(h3));
    }
}

// ---------------------------------------------------------------------------
extern "C" void kernel_launch(void* const* d_in, const int* in_sizes, int n_in,
                              void* d_out, int out_size)
{
    const float* x   = (const float*)d_in[0];
    const float* Wq  = (const float*)d_in[1];
    const float* Wk  = (const float*)d_in[2];
    const float* Wv  = (const float*)d_in[3];
    const float* Wo  = (const float*)d_in[4];
    const float* kvc = (const float*)d_in[5];
    const int*   bt  = (const int*)d_in[7];

    float* out   = (float*)d_out;
    float* cache = out + OUT_ELEMS;

    float *Qb, *Kb, *Vb;
    __nv_bfloat16 *xh, *xl, *AOh, *AOl;
    __nv_bfloat16 *Wqh, *Wql, *Wkh, *Wkl, *Wvh, *Wvl, *Woh, *Wol;
    cudaGetSymbolAddress((void**)&Qb,  g_Q);
    cudaGetSymbolAddress((void**)&Kb,  g_K);
    cudaGetSymbolAddress((void**)&Vb,  g_V);
    cudaGetSymbolAddress((void**)&xh,  g_xh);  cudaGetSymbolAddress((void**)&xl,  g_xl);
    cudaGetSymbolAddress((void**)&AOh, g_AOh); cudaGetSymbolAddress((void**)&AOl, g_AOl);
    cudaGetSymbolAddress((void**)&Wqh, g_Wqh); cudaGetSymbolAddress((void**)&Wql, g_Wql);
    cudaGetSymbolAddress((void**)&Wkh, g_Wkh); cudaGetSymbolAddress((void**)&Wkl, g_Wkl);
    cudaGetSymbolAddress((void**)&Wvh, g_Wvh); cudaGetSymbolAddress((void**)&Wvl, g_Wvl);
    cudaGetSymbolAddress((void**)&Woh, g_Woh); cudaGetSymbolAddress((void**)&Wol, g_Wol);

    cudaFuncSetAttribute(gemm_bf16x3_multi, cudaFuncAttributeMaxDynamicSharedMemorySize, GEMM_SMEM);
    cudaFuncSetAttribute(flash_attn_mma, cudaFuncAttributeMaxDynamicSharedMemorySize, ATT_SMEM);

    // Pack operands to bf16 hi/lo planes
    pack_split<<<(TOK * DM / 4) / 256, 256>>>(x,  xh,  xl,  TOK * DM / 4);
    pack_split<<<(DM * DM / 4) / 256, 256>>>(Wq, Wqh, Wql, DM * DM / 4);
    pack_split<<<(DM * DM / 4) / 256, 256>>>(Wk, Wkh, Wkl, DM * DM / 4);
    pack_split<<<(DM * DM / 4) / 256, 256>>>(Wv, Wvh, Wvl, DM * DM / 4);
    pack_split<<<(DM * DM / 4) / 256, 256>>>(Wo, Woh, Wol, DM * DM / 4);

    // Fused QKV GEMM
    gemm_bf16x3_multi<<<dim3(48, 64), 256, GEMM_SMEM>>>(
        xh, xl, Wqh, Wql, Wkh, Wkl, Wvh, Wvl, Qb, Kb, Vb);

    cudaMemcpyAsync(cache, kvc, (size_t)CACHE_ELEMS * sizeof(float),
                    cudaMemcpyDeviceToDevice);

    rope_scatter<<<(TOK * NH * 64) / 256, 256>>>(Qb, Kb, Vb, bt, cache);

    flash_attn_mma<<<dim3(SEQ / 128, 8 * NH), 256, ATT_SMEM>>>(Qb, Kb, Vb, AOh, AOl);

    // O GEMM
    gemm_bf16x3_multi<<<dim3(16, 64), 256, GEMM_SMEM>>>(
        AOh, AOl, Woh, Wol, Woh, Wol, Woh, Wol, out, out, out);
}

// round 15
// speedup vs baseline: 2.2672x; 1.0350x over previous
#include <cuda_runtime.h>
#include <cuda_bf16.h>
#include <cstdint>

// Problem constants
#define TOK   8192
#define DM    2048
#define NH    16
#define DH    128
#define SEQ   1024
#define BSZ   256
#define NBLK  64
#define CACHE_ELEMS (NBLK*2*NH*BSZ*DH)  // 33554432
#define OUT_ELEMS   (TOK*DM)            // 16777216

// Scratch (fp32 activations; Q/K/V get tf32-pre-rounded in rope_scatter)
__device__ float g_Q [TOK*DM];
__device__ float g_K [TOK*DM];
__device__ float g_V [TOK*DM];
// bf16 hi/lo planes for GEMM operands
__device__ __nv_bfloat16 g_xh [TOK*DM], g_xl [TOK*DM];
__device__ __nv_bfloat16 g_AOh[TOK*DM], g_AOl[TOK*DM];
__device__ __nv_bfloat16 g_Wqh[DM*DM], g_Wql[DM*DM];
__device__ __nv_bfloat16 g_Wkh[DM*DM], g_Wkl[DM*DM];
__device__ __nv_bfloat16 g_Wvh[DM*DM], g_Wvl[DM*DM];
__device__ __nv_bfloat16 g_Woh[DM*DM], g_Wol[DM*DM];

__device__ __forceinline__ uint32_t smem_u32(const void* p) {
    uint32_t a;
    asm("{ .reg .u64 t; cvta.to.shared.u64 t, %1; cvt.u32.u64 %0, t; }" : "=r"(a) : "l"(p));
    return a;
}
__device__ __forceinline__ uint32_t tf32_bits(float x) {
    uint32_t r; asm("cvt.rna.tf32.f32 %0, %1;" : "=r"(r) : "f"(x)); return r;
}
__device__ __forceinline__ void cp_async16(uint32_t dst, const void* src) {
    asm volatile("cp.async.ca.shared.global [%0], [%1], 16;" :: "r"(dst), "l"(src));
}
__device__ __forceinline__ void mma_tf32(float* d, const uint32_t* a, const uint32_t* b) {
    asm volatile(
        "mma.sync.aligned.m16n8k8.row.col.f32.tf32.tf32.f32 "
        "{%0,%1,%2,%3}, {%4,%5,%6,%7}, {%8,%9}, {%0,%1,%2,%3};"
        : "+f"(d[0]), "+f"(d[1]), "+f"(d[2]), "+f"(d[3])
        : "r"(a[0]), "r"(a[1]), "r"(a[2]), "r"(a[3]), "r"(b[0]), "r"(b[1]));
}
__device__ __forceinline__ void mma_bf16(float* d, const uint32_t* a, const uint32_t* b) {
    asm volatile(
        "mma.sync.aligned.m16n8k16.row.col.f32.bf16.bf16.f32 "
        "{%0,%1,%2,%3}, {%4,%5,%6,%7}, {%8,%9}, {%0,%1,%2,%3};"
        : "+f"(d[0]), "+f"(d[1]), "+f"(d[2]), "+f"(d[3])
        : "r"(a[0]), "r"(a[1]), "r"(a[2]), "r"(a[3]), "r"(b[0]), "r"(b[1]));
}
__device__ __forceinline__ uint32_t pack_bf2(float x, float y) {
    __nv_bfloat16 hx = __float2bfloat16_rn(x);
    __nv_bfloat16 hy = __float2bfloat16_rn(y);
    return (uint32_t)__bfloat16_as_ushort(hx) | ((uint32_t)__bfloat16_as_ushort(hy) << 16);
}

// ---------------------------------------------------------------------------
// Pack fp32 -> (hi, lo) bf16 planes. 4 elems/thread.
// ---------------------------------------------------------------------------
__global__ void __launch_bounds__(256) pack_split(const float* __restrict__ s,
                                                  __nv_bfloat16* __restrict__ h,
                                                  __nv_bfloat16* __restrict__ l,
                                                  int n4)
{
    int i = blockIdx.x * 256 + threadIdx.x;
    if (i >= n4) return;
    float4 v = ((const float4*)s)[i];
    __nv_bfloat16 h0 = __float2bfloat16_rn(v.x), h1 = __float2bfloat16_rn(v.y);
    __nv_bfloat16 h2 = __float2bfloat16_rn(v.z), h3 = __float2bfloat16_rn(v.w);
    float r0 = v.x - __bfloat162float(h0), r1 = v.y - __bfloat162float(h1);
    float r2 = v.z - __bfloat162float(h2), r3 = v.w - __bfloat162float(h3);
    uint32_t hA = (uint32_t)__bfloat16_as_ushort(h0) | ((uint32_t)__bfloat16_as_ushort(h1) << 16);
    uint32_t hB = (uint32_t)__bfloat16_as_ushort(h2) | ((uint32_t)__bfloat16_as_ushort(h3) << 16);
    *(uint2*)&h[4 * (size_t)i] = make_uint2(hA, hB);
    *(uint2*)&l[4 * (size_t)i] = make_uint2(pack_bf2(r0, r1), pack_bf2(r2, r3));
}

// ---------------------------------------------------------------------------
// bf16 2-split GEMM (unchanged from R13 — verified).
// ---------------------------------------------------------------------------
#define GK 2048
#define BBK 32
#define GNSTEP (GK / BBK)
#define PLANE_B 10240
#define STAGE_B (4 * PLANE_B)
#define GEMM_SMEM (2 * STAGE_B)

__global__ void __launch_bounds__(256, 1) gemm_bf16x3_multi(
    const __nv_bfloat16* __restrict__ Ah, const __nv_bfloat16* __restrict__ Al,
    const __nv_bfloat16* __restrict__ B0h, const __nv_bfloat16* __restrict__ B0l,
    const __nv_bfloat16* __restrict__ B1h, const __nv_bfloat16* __restrict__ B1l,
    const __nv_bfloat16* __restrict__ B2h, const __nv_bfloat16* __restrict__ B2l,
    float* __restrict__ C0, float* __restrict__ C1, float* __restrict__ C2)
{
    extern __shared__ uint32_t smu[];
    const uint32_t sbase = smem_u32(smu);

    const int sel = blockIdx.x >> 4;
    const __nv_bfloat16* Bh = (sel == 0) ? B0h : (sel == 1) ? B1h : B2h;
    const __nv_bfloat16* Bl = (sel == 0) ? B0l : (sel == 1) ? B1l : B2l;
    float*               C  = (sel == 0) ? C0  : (sel == 1) ? C1  : C2;

    const int tid  = threadIdx.x;
    const int lane = tid & 31;
    const int wid  = tid >> 5;
    const int wm   = wid & 1;
    const int wn   = wid >> 1;
    const int bm   = blockIdx.y * 128;
    const int bn   = (blockIdx.x & 15) * 128;
    const int r0   = lane >> 2;
    const int c0   = lane & 3;

    const int ldrow = tid >> 2;
    const int ldch  = tid & 3;
    const __nv_bfloat16* Ah_t = Ah + (size_t)(bm + ldrow) * GK + ldch * 8;
    const __nv_bfloat16* Al_t = Al + (size_t)(bm + ldrow) * GK + ldch * 8;
    const __nv_bfloat16* Bh_t = Bh + (size_t)(bn + ldrow) * GK + ldch * 8;
    const __nv_bfloat16* Bl_t = Bl + (size_t)(bn + ldrow) * GK + ldch * 8;
    const uint32_t sdst = sbase + ldrow * 80 + ldch * 16;

    #define LOAD_TILES(KIDX, BUF) do {                                           \
        const int _k0 = (KIDX) * BBK;                                            \
        const uint32_t _d = sdst + (BUF) * STAGE_B;                              \
        _Pragma("unroll")                                                        \
        for (int _i = 0; _i < 2; _i++) {                                         \
            const size_t _g = (size_t)_i * 64 * GK + _k0;                        \
            const uint32_t _o = _i * 64 * 80;                                    \
            cp_async16(_d + _o,               Ah_t + _g);                        \
            cp_async16(_d + _o + PLANE_B,     Al_t + _g);                        \
            cp_async16(_d + _o + 2*PLANE_B,   Bh_t + _g);                        \
            cp_async16(_d + _o + 3*PLANE_B,   Bl_t + _g);                        \
        }                                                                        \
        asm volatile("cp.async.commit_group;");                                  \
    } while (0)

    float acc[4][4][4];
    #pragma unroll
    for (int mi = 0; mi < 4; mi++)
        #pragma unroll
        for (int nj = 0; nj < 4; nj++)
            #pragma unroll
            for (int r = 0; r < 4; r++) acc[mi][nj][r] = 0.0f;

    LOAD_TILES(0, 0);

    for (int s = 0; s < GNSTEP; s++) {
        const int buf = s & 1;
        if (s + 1 < GNSTEP) {
            LOAD_TILES(s + 1, buf ^ 1);
            asm volatile("cp.async.wait_group 1;");
        } else {
            asm volatile("cp.async.wait_group 0;");
        }
        __syncthreads();

        const uint32_t* P   = smu + buf * (STAGE_B / 4);
        const uint32_t* PAh = P;
        const uint32_t* PAl = P + PLANE_B / 4;
        const uint32_t* PBh = P + 2 * PLANE_B / 4;
        const uint32_t* PBl = P + 3 * PLANE_B / 4;

        #pragma unroll
        for (int kk = 0; kk < 2; kk++) {
            uint32_t ah[4][4], al[4][4], bh[4][2], bl[4][2];
            #pragma unroll
            for (int mi = 0; mi < 4; mi++) {
                const int idx = (wm * 64 + mi * 16 + r0) * 20 + kk * 8 + c0;
                ah[mi][0] = PAh[idx];       ah[mi][1] = PAh[idx + 160];
                ah[mi][2] = PAh[idx + 4];   ah[mi][3] = PAh[idx + 164];
                al[mi][0] = PAl[idx];       al[mi][1] = PAl[idx + 160];
                al[mi][2] = PAl[idx + 4];   al[mi][3] = PAl[idx + 164];
            }
            #pragma unroll
            for (int nj = 0; nj < 4; nj++) {
                const int nidx = (wn * 32 + nj * 8 + r0) * 20 + kk * 8 + c0;
                bh[nj][0] = PBh[nidx];      bh[nj][1] = PBh[nidx + 4];
                bl[nj][0] = PBl[nidx];      bl[nj][1] = PBl[nidx + 4];
            }
            #pragma unroll
            for (int mi = 0; mi < 4; mi++)
                #pragma unroll
                for (int nj = 0; nj < 4; nj++) {
                    mma_bf16(acc[mi][nj], ah[mi], bl[nj]);
                    mma_bf16(acc[mi][nj], al[mi], bh[nj]);
                    mma_bf16(acc[mi][nj], ah[mi], bh[nj]);
                }
        }
        __syncthreads();
    }

    #pragma unroll
    for (int mi = 0; mi < 4; mi++) {
        const int grow = bm + wm * 64 + mi * 16 + r0;
        #pragma unroll
        for (int nj = 0; nj < 4; nj++) {
            const int gcol = bn + wn * 32 + nj * 8 + c0 * 2;
            *(float2*)&C[(size_t)grow * DM + gcol]       = make_float2(acc[mi][nj][0], acc[mi][nj][1]);
            *(float2*)&C[(size_t)(grow + 8) * DM + gcol] = make_float2(acc[mi][nj][2], acc[mi][nj][3]);
        }
    }
}

// ---------------------------------------------------------------------------
// RoPE + paged-KV scatter. Writes EXACT fp32 k/v to cache, then stores
// tf32-pre-rounded values (Q also pre-scaled by 1/sqrt(DH)) back to Q/K/V.
// ---------------------------------------------------------------------------
__global__ void __launch_bounds__(256) rope_scatter(float* __restrict__ Q,
                                                    float* __restrict__ K,
                                                    float* __restrict__ V,
                                                    const int* __restrict__ block_table,
                                                    float* __restrict__ cache)
{
    int idx = blockIdx.x * blockDim.x + threadIdx.x;
    int i = idx & 63;
    int h = (idx >> 6) & (NH - 1);
    int t = idx >> 10;
    if (t >= TOK) return;

    const float scale = 0.08838834764831845f; // 1/sqrt(128)
    int pos = t & (SEQ - 1);
    float inv_freq = __powf(10000.0f, -(float)(2 * i) / 128.0f);
    float ang = (float)pos * inv_freq;
    float s, c;
    __sincosf(ang, &s, &c);

    size_t base = (size_t)t * DM + h * DH + i;
    float q1 = Q[base], q2 = Q[base + 64];
    float q1r = q1 * c - q2 * s;
    float q2r = q2 * c + q1 * s;

    float k1 = K[base], k2 = K[base + 64];
    float k1r = k1 * c - k2 * s;
    float k2r = k2 * c + k1 * s;

    float v1 = V[base], v2 = V[base + 64];

    // exact cache write
    int seq     = t >> 10;
    int logical = (t & (SEQ - 1)) >> 8;
    int phys    = block_table[seq * (SEQ / BSZ) + logical];
    int off     = t & (BSZ - 1);
    size_t kbase = (size_t)phys * (2 * NH * BSZ * DH) + (size_t)h * (BSZ * DH)
                 + (size_t)off * DH + i;
    cache[kbase]      = k1r;
    cache[kbase + 64] = k2r;
    size_t vbase = kbase + (size_t)NH * BSZ * DH;
    cache[vbase]      = v1;
    cache[vbase + 64] = v2;

    // tf32 pre-rounded attention operands
    Q[base]      = __uint_as_float(tf32_bits(q1r * scale));
    Q[base + 64] = __uint_as_float(tf32_bits(q2r * scale));
    K[base]      = __uint_as_float(tf32_bits(k1r));
    K[base + 64] = __uint_as_float(tf32_bits(k2r));
    V[base]      = __uint_as_float(tf32_bits(v1));
    V[base + 64] = __uint_as_float(tf32_bits(v2));
}

// ---------------------------------------------------------------------------
// Flash attention, tf32 mma, cp.async double-buffered K/V, Q in registers.
// BM=128 queries/CTA (8 warps x 16 rows), BN=64 keys/tile.
// ---------------------------------------------------------------------------
#define KV_STRIDE 132
#define PS_STRIDE 68
#define KV_TILE_U (64 * KV_STRIDE)                       // u32 per K or V stage
#define ATT_SMEM ((4 * KV_TILE_U + 128 * PS_STRIDE) * 4) // 169984 bytes

__global__ void __launch_bounds__(256, 1) flash_attn_mma(const float* __restrict__ Q,
                                                         const float* __restrict__ K,
                                                         const float* __restrict__ V,
                                                         __nv_bfloat16* __restrict__ Oh,
                                                         __nv_bfloat16* __restrict__ Ol)
{
    extern __shared__ uint32_t smu[];
    const uint32_t sbase = smem_u32(smu);
    uint32_t* Ps = smu + 4 * KV_TILE_U;

    const int qt   = blockIdx.x;
    const int bh   = blockIdx.y;
    const int b    = bh >> 4;
    const int h    = bh & 15;
    const int tid  = threadIdx.x;
    const int warp = tid >> 5;
    const int lane = tid & 31;
    const int r0   = lane >> 2;
    const int c0   = lane & 3;
    const int tok0 = b * SEQ;

    // FULL-tile cp.async loader: 2048 float4 per K and V tile (R13-verified
    // addressing: idx -> row = idx>>5, float-col = (idx&31)*4).
    #define ATT_LOAD(KT, STG) do {                                               \
        const uint32_t _kd = sbase + (STG) * KV_TILE_U * 4;                      \
        const uint32_t _vd = _kd + 2 * KV_TILE_U * 4;                            \
        _Pragma("unroll")                                                        \
        for (int _i = 0; _i < 8; _i++) {                                         \
            const int _idx = tid + _i * 256;                                     \
            const int _row = _idx >> 5;                                          \
            const int _c4  = (_idx & 31) * 4;                                    \
            const size_t _g = (size_t)(tok0 + (KT) * 64 + _row) * DM             \
                              + h * DH + _c4;                                    \
            const uint32_t _off = _row * (KV_STRIDE * 4) + _c4 * 4;              \
            cp_async16(_kd + _off, &K[_g]);                                      \
            cp_async16(_vd + _off, &V[_g]);                                      \
        }                                                                        \
        asm volatile("cp.async.commit_group;");                                  \
    } while (0)

    // Q fragments in registers (Q already tf32-rounded & scaled)
    uint32_t qf[16][4];
    {
        const uint32_t* Qr0 = (const uint32_t*)&Q[(size_t)(tok0 + qt * 128 + warp * 16 + r0) * DM + h * DH];
        const uint32_t* Qr1 = (const uint32_t*)&Q[(size_t)(tok0 + qt * 128 + warp * 16 + r0 + 8) * DM + h * DH];
        #pragma unroll
        for (int kk = 0; kk < 16; kk++) {
            qf[kk][0] = Qr0[kk * 8 + c0];
            qf[kk][1] = Qr1[kk * 8 + c0];
            qf[kk][2] = Qr0[kk * 8 + c0 + 4];
            qf[kk][3] = Qr1[kk * 8 + c0 + 4];
        }
    }

    float m0 = -1e30f, m1 = -1e30f, l0 = 0.0f, l1 = 0.0f;
    float acc[16][4];
    #pragma unroll
    for (int j = 0; j < 16; j++)
        #pragma unroll
        for (int r = 0; r < 4; r++) acc[j][r] = 0.0f;

    const int ktmax = 2 * qt + 1;
    ATT_LOAD(0, 0);

    for (int kt = 0; kt <= ktmax; kt++) {
        const int cur = kt & 1;
        if (kt < ktmax) {
            ATT_LOAD(kt + 1, cur ^ 1);
            asm volatile("cp.async.wait_group 1;");
        } else {
            asm volatile("cp.async.wait_group 0;");
        }
        __syncthreads();

        const uint32_t* Ksb = smu + cur * KV_TILE_U;
        const uint32_t* Vsb = smu + (2 + cur) * KV_TILE_U;

        // S = Q K^T
        float s[8][4];
        #pragma unroll
        for (int j = 0; j < 8; j++)
            #pragma unroll
            for (int r = 0; r < 4; r++) s[j][r] = 0.0f;

        #pragma unroll
        for (int kk = 0; kk < 16; kk++) {
            const int kc = kk * 8 + c0;
            #pragma unroll
            for (int j = 0; j < 8; j++) {
                uint32_t bf[2];
                bf[0] = Ksb[(j * 8 + r0) * KV_STRIDE + kc];
                bf[1] = Ksb[(j * 8 + r0) * KV_STRIDE + kc + 4];
                mma_tf32(s[j], qf[kk], bf);
            }
        }

        if (kt >= 2 * qt) {
            const int grow0 = qt * 128 + warp * 16 + r0;
            #pragma unroll
            for (int j = 0; j < 8; j++) {
                const int gcol = kt * 64 + j * 8 + 2 * c0;
                if (gcol     > grow0)     s[j][0] = -1e30f;
                if (gcol + 1 > grow0)     s[j][1] = -1e30f;
                if (gcol     > grow0 + 8) s[j][2] = -1e30f;
                if (gcol + 1 > grow0 + 8) s[j][3] = -1e30f;
            }
        }

        // warp-private online softmax
        float mx0 = -1e30f, mx1 = -1e30f;
        #pragma unroll
        for (int j = 0; j < 8; j++) {
            mx0 = fmaxf(mx0, fmaxf(s[j][0], s[j][1]));
            mx1 = fmaxf(mx1, fmaxf(s[j][2], s[j][3]));
        }
        mx0 = fmaxf(mx0, __shfl_xor_sync(0xffffffffu, mx0, 1));
        mx0 = fmaxf(mx0, __shfl_xor_sync(0xffffffffu, mx0, 2));
        mx1 = fmaxf(mx1, __shfl_xor_sync(0xffffffffu, mx1, 1));
        mx1 = fmaxf(mx1, __shfl_xor_sync(0xffffffffu, mx1, 2));

        const float mn0 = fmaxf(m0, mx0);
        const float mn1 = fmaxf(m1, mx1);
        const float corr0 = __expf(m0 - mn0);
        const float corr1 = __expf(m1 - mn1);
        float ls0 = 0.0f, ls1 = 0.0f;
        const int prow0 = warp * 16 + r0;
        #pragma unroll
        for (int j = 0; j < 8; j++) {
            float p0 = __expf(s[j][0] - mn0);
            float p1 = __expf(s[j][1] - mn0);
            float p2 = __expf(s[j][2] - mn1);
            float p3 = __expf(s[j][3] - mn1);
            ls0 += p0 + p1;
            ls1 += p2 + p3;
            Ps[prow0 * PS_STRIDE + j * 8 + 2 * c0]           = tf32_bits(p0);
            Ps[prow0 * PS_STRIDE + j * 8 + 2 * c0 + 1]       = tf32_bits(p1);
            Ps[(prow0 + 8) * PS_STRIDE + j * 8 + 2 * c0]     = tf32_bits(p2);
            Ps[(prow0 + 8) * PS_STRIDE + j * 8 + 2 * c0 + 1] = tf32_bits(p3);
        }
        ls0 += __shfl_xor_sync(0xffffffffu, ls0, 1);
        ls0 += __shfl_xor_sync(0xffffffffu, ls0, 2);
        ls1 += __shfl_xor_sync(0xffffffffu, ls1, 1);
        ls1 += __shfl_xor_sync(0xffffffffu, ls1, 2);
        l0 = l0 * corr0 + ls0;  m0 = mn0;
        l1 = l1 * corr1 + ls1;  m1 = mn1;

        #pragma unroll
        for (int j = 0; j < 16; j++) {
            acc[j][0] *= corr0; acc[j][1] *= corr0;
            acc[j][2] *= corr1; acc[j][3] *= corr1;
        }
        __syncwarp();

        // O += P V
        #pragma unroll
        for (int kk = 0; kk < 8; kk++) {
            const int kc = kk * 8 + c0;
            uint32_t af[4];
            af[0] = Ps[prow0 * PS_STRIDE + kc];
            af[1] = Ps[(prow0 + 8) * PS_STRIDE + kc];
            af[2] = Ps[prow0 * PS_STRIDE + kc + 4];
            af[3] = Ps[(prow0 + 8) * PS_STRIDE + kc + 4];
            #pragma unroll
            for (int j = 0; j < 16; j++) {
                uint32_t bf[2];
                bf[0] = Vsb[kc * KV_STRIDE + j * 8 + r0];
                bf[1] = Vsb[(kc + 4) * KV_STRIDE + j * 8 + r0];
                mma_tf32(acc[j], af, bf);
            }
        }
        __syncthreads();   // stage cur free for kt+2 prefetch
    }

    // epilogue: normalize, split to bf16 hi/lo planes
    const float inv0 = 1.0f / l0;
    const float inv1 = 1.0f / l1;
    const size_t row0 = (size_t)(tok0 + qt * 128 + warp * 16 + r0);
    #pragma unroll
    for (int j = 0; j < 16; j++) {
        const int col = h * DH + j * 8 + 2 * c0;
        float o0 = acc[j][0] * inv0, o1 = acc[j][1] * inv0;
        float o2 = acc[j][2] * inv1, o3 = acc[j][3] * inv1;
        __nv_bfloat16 h0 = __float2bfloat16_rn(o0), h1 = __float2bfloat16_rn(o1);
        __nv_bfloat16 h2 = __float2bfloat16_rn(o2), h3 = __float2bfloat16_rn(o3);
        size_t off0 = row0 * DM + col;
        size_t off1 = (row0 + 8) * DM + col;
        *(uint32_t*)&Oh[off0] = (uint32_t)__bfloat16_as_ushort(h0) | ((uint32_t)__bfloat16_as_ushort(h1) << 16);
        *(uint32_t*)&Oh[off1] = (uint32_t)__bfloat16_as_ushort(h2) | ((uint32_t)__bfloat16_as_ushort(h3) << 16);
        *(uint32_t*)&Ol[off0] = pack_bf2(o0 - __bfloat162float(h0), o1 - __bfloat162float(h1));
        *(uint32_t*)&Ol[off1] = pack_bf2(o2 - __bfloat162float(h2), o3 - __bfloat162float(h3));
    }
}

// ---------------------------------------------------------------------------
extern "C" void kernel_launch(void* const* d_in, const int* in_sizes, int n_in,
                              void* d_out, int out_size)
{
    const float* x   = (const float*)d_in[0];
    const float* Wq  = (const float*)d_in[1];
    const float* Wk  = (const float*)d_in[2];
    const float* Wv  = (const float*)d_in[3];
    const float* Wo  = (const float*)d_in[4];
    const float* kvc = (const float*)d_in[5];
    const int*   bt  = (const int*)d_in[7];

    float* out   = (float*)d_out;
    float* cache = out + OUT_ELEMS;

    float *Qb, *Kb, *Vb;
    __nv_bfloat16 *xh, *xl, *AOh, *AOl;
    __nv_bfloat16 *Wqh, *Wql, *Wkh, *Wkl, *Wvh, *Wvl, *Woh, *Wol;
    cudaGetSymbolAddress((void**)&Qb,  g_Q);
    cudaGetSymbolAddress((void**)&Kb,  g_K);
    cudaGetSymbolAddress((void**)&Vb,  g_V);
    cudaGetSymbolAddress((void**)&xh,  g_xh);  cudaGetSymbolAddress((void**)&xl,  g_xl);
    cudaGetSymbolAddress((void**)&AOh, g_AOh); cudaGetSymbolAddress((void**)&AOl, g_AOl);
    cudaGetSymbolAddress((void**)&Wqh, g_Wqh); cudaGetSymbolAddress((void**)&Wql, g_Wql);
    cudaGetSymbolAddress((void**)&Wkh, g_Wkh); cudaGetSymbolAddress((void**)&Wkl, g_Wkl);
    cudaGetSymbolAddress((void**)&Wvh, g_Wvh); cudaGetSymbolAddress((void**)&Wvl, g_Wvl);
    cudaGetSymbolAddress((void**)&Woh, g_Woh); cudaGetSymbolAddress((void**)&Wol, g_Wol);

    cudaFuncSetAttribute(gemm_bf16x3_multi, cudaFuncAttributeMaxDynamicSharedMemorySize, GEMM_SMEM);
    cudaFuncSetAttribute(flash_attn_mma, cudaFuncAttributeMaxDynamicSharedMemorySize, ATT_SMEM);

    pack_split<<<(TOK * DM / 4) / 256, 256>>>(x,  xh,  xl,  TOK * DM / 4);
    pack_split<<<(DM * DM / 4) / 256, 256>>>(Wq, Wqh, Wql, DM * DM / 4);
    pack_split<<<(DM * DM / 4) / 256, 256>>>(Wk, Wkh, Wkl, DM * DM / 4);
    pack_split<<<(DM * DM / 4) / 256, 256>>>(Wv, Wvh, Wvl, DM * DM / 4);
    pack_split<<<(DM * DM / 4) / 256, 256>>>(Wo, Woh, Wol, DM * DM / 4);

    gemm_bf16x3_multi<<<dim3(48, 64), 256, GEMM_SMEM>>>(
        xh, xl, Wqh, Wql, Wkh, Wkl, Wvh, Wvl, Qb, Kb, Vb);

    cudaMemcpyAsync(cache, kvc, (size_t)CACHE_ELEMS * sizeof(float),
                    cudaMemcpyDeviceToDevice);

    rope_scatter<<<(TOK * NH * 64) / 256, 256>>>(Qb, Kb, Vb, bt, cache);

    flash_attn_mma<<<dim3(SEQ / 128, 8 * NH), 256, ATT_SMEM>>>(Qb, Kb, Vb, AOh, AOl);

    gemm_bf16x3_multi<<<dim3(16, 64), 256, GEMM_SMEM>>>(
        AOh, AOl, Woh, Wol, Woh, Wol, Woh, Wol, out, out, out);
}

// round 16
// speedup vs baseline: 4.4230x; 1.9508x over previous
#include <cuda_runtime.h>
#include <cuda_fp16.h>
#include <cuda_bf16.h>
#include <cstdint>

// Problem constants
#define TOK   8192
#define DM    2048
#define NH    16
#define DH    128
#define SEQ   1024
#define BSZ   256
#define NBLK  64
#define CACHE_ELEMS (NBLK*2*NH*BSZ*DH)  // 33554432
#define OUT_ELEMS   (TOK*DM)            // 16777216

// Scratch (fp32 activations; Q/K/V get tf32-pre-rounded in rope_scatter)
__device__ float g_Q [TOK*DM];
__device__ float g_K [TOK*DM];
__device__ float g_V [TOK*DM];
// fp16 planes for GEMM operands (single-rounded)
__device__ __half g_xh [TOK*DM];
__device__ __half g_AOh[TOK*DM];
__device__ __half g_Wqh[DM*DM];
__device__ __half g_Wkh[DM*DM];
__device__ __half g_Wvh[DM*DM];
__device__ __half g_Woh[DM*DM];

__device__ __forceinline__ uint32_t smem_u32(const void* p) {
    uint32_t a;
    asm("{ .reg .u64 t; cvta.to.shared.u64 t, %1; cvt.u32.u64 %0, t; }" : "=r"(a) : "l"(p));
    return a;
}
__device__ __forceinline__ uint32_t tf32_bits(float x) {
    uint32_t r; asm("cvt.rna.tf32.f32 %0, %1;" : "=r"(r) : "f"(x)); return r;
}
__device__ __forceinline__ void cp_async16(uint32_t dst, const void* src) {
    asm volatile("cp.async.ca.shared.global [%0], [%1], 16;" :: "r"(dst), "l"(src));
}
// tf32 m16n8k8 (attention) — verified mapping
__device__ __forceinline__ void mma_tf32(float* d, const uint32_t* a, const uint32_t* b) {
    asm volatile(
        "mma.sync.aligned.m16n8k8.row.col.f32.tf32.tf32.f32 "
        "{%0,%1,%2,%3}, {%4,%5,%6,%7}, {%8,%9}, {%0,%1,%2,%3};"
        : "+f"(d[0]), "+f"(d[1]), "+f"(d[2]), "+f"(d[3])
        : "r"(a[0]), "r"(a[1]), "r"(a[2]), "r"(a[3]), "r"(b[0]), "r"(b[1]));
}
// fp16 m16n8k16 (GEMM) — fragment layout identical to the verified bf16 k16 path
__device__ __forceinline__ void mma_fp16(float* d, const uint32_t* a, const uint32_t* b) {
    asm volatile(
        "mma.sync.aligned.m16n8k16.row.col.f32.f16.f16.f32 "
        "{%0,%1,%2,%3}, {%4,%5,%6,%7}, {%8,%9}, {%0,%1,%2,%3};"
        : "+f"(d[0]), "+f"(d[1]), "+f"(d[2]), "+f"(d[3])
        : "r"(a[0]), "r"(a[1]), "r"(a[2]), "r"(a[3]), "r"(b[0]), "r"(b[1]));
}
__device__ __forceinline__ uint32_t pack_h2(float x, float y) {
    __half hx = __float2half_rn(x);
    __half hy = __float2half_rn(y);
    return (uint32_t)__half_as_ushort(hx) | ((uint32_t)__half_as_ushort(hy) << 16);
}

// ---------------------------------------------------------------------------
// Pack fp32 -> fp16 plane. 4 elems/thread.
// ---------------------------------------------------------------------------
__global__ void __launch_bounds__(256) pack_half(const float* __restrict__ s,
                                                 __half* __restrict__ h,
                                                 int n4)
{
    int i = blockIdx.x * 256 + threadIdx.x;
    if (i >= n4) return;
    float4 v = ((const float4*)s)[i];
    *(uint2*)&h[4 * (size_t)i] = make_uint2(pack_h2(v.x, v.y), pack_h2(v.z, v.w));
}

// ---------------------------------------------------------------------------
// fp16 single-pass GEMM: C[M,N] = A[M,K] * B[N,K]^T  (K contiguous).
// CTA 128x128x32, 256 thr (8 warps = 2m x 4n), warp 64x32, 1 MMA per frag pair.
// smem per stage: 2 planes (A,B), 128 rows x 80 B (64 B data + 16 pad).
// ---------------------------------------------------------------------------
#define GK 2048
#define BBK 32
#define GNSTEP (GK / BBK)        // 64
#define PLANE_B 10240            // 128 * 80
#define STAGE_B (2 * PLANE_B)    // 20480
#define GEMM_SMEM (2 * STAGE_B)  // 40960

__global__ void __launch_bounds__(256, 1) gemm_fp16_multi(
    const __half* __restrict__ Ah,
    const __half* __restrict__ B0, const __half* __restrict__ B1, const __half* __restrict__ B2,
    float* __restrict__ C0, float* __restrict__ C1, float* __restrict__ C2)
{
    extern __shared__ uint32_t smu[];
    const uint32_t sbase = smem_u32(smu);

    const int sel = blockIdx.x >> 4;
    const __half* B = (sel == 0) ? B0 : (sel == 1) ? B1 : B2;
    float*        C = (sel == 0) ? C0 : (sel == 1) ? C1 : C2;

    const int tid  = threadIdx.x;
    const int lane = tid & 31;
    const int wid  = tid >> 5;
    const int wm   = wid & 1;
    const int wn   = wid >> 1;
    const int bm   = blockIdx.y * 128;
    const int bn   = (blockIdx.x & 15) * 128;
    const int r0   = lane >> 2;
    const int c0   = lane & 3;

    // cp.async: thread -> rows (tid>>2) and +64 per plane, 16B chunk (tid&3)
    const int ldrow = tid >> 2;
    const int ldch  = tid & 3;
    const __half* A_t = Ah + (size_t)(bm + ldrow) * GK + ldch * 8;
    const __half* B_t = B  + (size_t)(bn + ldrow) * GK + ldch * 8;
    const uint32_t sdst = sbase + ldrow * 80 + ldch * 16;

    #define LOAD_TILES(KIDX, BUF) do {                                           \
        const int _k0 = (KIDX) * BBK;                                            \
        const uint32_t _d = sdst + (BUF) * STAGE_B;                              \
        _Pragma("unroll")                                                        \
        for (int _i = 0; _i < 2; _i++) {                                         \
            const size_t _g = (size_t)_i * 64 * GK + _k0;                        \
            const uint32_t _o = _i * 64 * 80;                                    \
            cp_async16(_d + _o,           A_t + _g);                             \
            cp_async16(_d + _o + PLANE_B, B_t + _g);                             \
        }                                                                        \
        asm volatile("cp.async.commit_group;");                                  \
    } while (0)

    float acc[4][4][4];
    #pragma unroll
    for (int mi = 0; mi < 4; mi++)
        #pragma unroll
        for (int nj = 0; nj < 4; nj++)
            #pragma unroll
            for (int r = 0; r < 4; r++) acc[mi][nj][r] = 0.0f;

    LOAD_TILES(0, 0);

    for (int s = 0; s < GNSTEP; s++) {
        const int buf = s & 1;
        if (s + 1 < GNSTEP) {
            LOAD_TILES(s + 1, buf ^ 1);
            asm volatile("cp.async.wait_group 1;");
        } else {
            asm volatile("cp.async.wait_group 0;");
        }
        __syncthreads();

        const uint32_t* P  = smu + buf * (STAGE_B / 4);
        const uint32_t* PA = P;
        const uint32_t* PB = P + PLANE_B / 4;

        #pragma unroll
        for (int kk = 0; kk < 2; kk++) {
            uint32_t af[4][4], bf[4][2];
            #pragma unroll
            for (int mi = 0; mi < 4; mi++) {
                const int idx = (wm * 64 + mi * 16 + r0) * 20 + kk * 8 + c0;
                af[mi][0] = PA[idx];       af[mi][1] = PA[idx + 160];
                af[mi][2] = PA[idx + 4];   af[mi][3] = PA[idx + 164];
            }
            #pragma unroll
            for (int nj = 0; nj < 4; nj++) {
                const int nidx = (wn * 32 + nj * 8 + r0) * 20 + kk * 8 + c0;
                bf[nj][0] = PB[nidx];      bf[nj][1] = PB[nidx + 4];
            }
            #pragma unroll
            for (int mi = 0; mi < 4; mi++)
                #pragma unroll
                for (int nj = 0; nj < 4; nj++)
                    mma_fp16(acc[mi][nj], af[mi], bf[nj]);
        }
        __syncthreads();
    }

    #pragma unroll
    for (int mi = 0; mi < 4; mi++) {
        const int grow = bm + wm * 64 + mi * 16 + r0;
        #pragma unroll
        for (int nj = 0; nj < 4; nj++) {
            const int gcol = bn + wn * 32 + nj * 8 + c0 * 2;
            *(float2*)&C[(size_t)grow * DM + gcol]       = make_float2(acc[mi][nj][0], acc[mi][nj][1]);
            *(float2*)&C[(size_t)(grow + 8) * DM + gcol] = make_float2(acc[mi][nj][2], acc[mi][nj][3]);
        }
    }
}

// ---------------------------------------------------------------------------
// RoPE + paged-KV scatter. Exact fp32 cache write; tf32 pre-round Q/K/V.
// ---------------------------------------------------------------------------
__global__ void __launch_bounds__(256) rope_scatter(float* __restrict__ Q,
                                                    float* __restrict__ K,
                                                    float* __restrict__ V,
                                                    const int* __restrict__ block_table,
                                                    float* __restrict__ cache)
{
    int idx = blockIdx.x * blockDim.x + threadIdx.x;
    int i = idx & 63;
    int h = (idx >> 6) & (NH - 1);
    int t = idx >> 10;
    if (t >= TOK) return;

    const float scale = 0.08838834764831845f; // 1/sqrt(128)
    int pos = t & (SEQ - 1);
    float inv_freq = __powf(10000.0f, -(float)(2 * i) / 128.0f);
    float ang = (float)pos * inv_freq;
    float s, c;
    __sincosf(ang, &s, &c);

    size_t base = (size_t)t * DM + h * DH + i;
    float q1 = Q[base], q2 = Q[base + 64];
    float q1r = q1 * c - q2 * s;
    float q2r = q2 * c + q1 * s;

    float k1 = K[base], k2 = K[base + 64];
    float k1r = k1 * c - k2 * s;
    float k2r = k2 * c + k1 * s;

    float v1 = V[base], v2 = V[base + 64];

    int seq     = t >> 10;
    int logical = (t & (SEQ - 1)) >> 8;
    int phys    = block_table[seq * (SEQ / BSZ) + logical];
    int off     = t & (BSZ - 1);
    size_t kbase = (size_t)phys * (2 * NH * BSZ * DH) + (size_t)h * (BSZ * DH)
                 + (size_t)off * DH + i;
    cache[kbase]      = k1r;
    cache[kbase + 64] = k2r;
    size_t vbase = kbase + (size_t)NH * BSZ * DH;
    cache[vbase]      = v1;
    cache[vbase + 64] = v2;

    Q[base]      = __uint_as_float(tf32_bits(q1r * scale));
    Q[base + 64] = __uint_as_float(tf32_bits(q2r * scale));
    K[base]      = __uint_as_float(tf32_bits(k1r));
    K[base + 64] = __uint_as_float(tf32_bits(k2r));
    V[base]      = __uint_as_float(tf32_bits(v1));
    V[base + 64] = __uint_as_float(tf32_bits(v2));
}

// ---------------------------------------------------------------------------
// Flash attention, tf32 mma, cp.async double-buffered K/V, Q in registers.
// BM=128 queries/CTA (8 warps x 16 rows), BN=64 keys/tile. (R15-verified.)
// Epilogue writes AO as a single fp16 plane.
// ---------------------------------------------------------------------------
#define KV_STRIDE 132
#define PS_STRIDE 68
#define KV_TILE_U (64 * KV_STRIDE)
#define ATT_SMEM ((4 * KV_TILE_U + 128 * PS_STRIDE) * 4) // 169984 bytes

__global__ void __launch_bounds__(256, 1) flash_attn_mma(const float* __restrict__ Q,
                                                         const float* __restrict__ K,
                                                         const float* __restrict__ V,
                                                         __half* __restrict__ Oh)
{
    extern __shared__ uint32_t smu[];
    const uint32_t sbase = smem_u32(smu);
    uint32_t* Ps = smu + 4 * KV_TILE_U;

    const int qt   = blockIdx.x;
    const int bh   = blockIdx.y;
    const int b    = bh >> 4;
    const int h    = bh & 15;
    const int tid  = threadIdx.x;
    const int warp = tid >> 5;
    const int lane = tid & 31;
    const int r0   = lane >> 2;
    const int c0   = lane & 3;
    const int tok0 = b * SEQ;

    #define ATT_LOAD(KT, STG) do {                                               \
        const uint32_t _kd = sbase + (STG) * KV_TILE_U * 4;                      \
        const uint32_t _vd = _kd + 2 * KV_TILE_U * 4;                            \
        _Pragma("unroll")                                                        \
        for (int _i = 0; _i < 8; _i++) {                                         \
            const int _idx = tid + _i * 256;                                     \
            const int _row = _idx >> 5;                                          \
            const int _c4  = (_idx & 31) * 4;                                    \
            const size_t _g = (size_t)(tok0 + (KT) * 64 + _row) * DM             \
                              + h * DH + _c4;                                    \
            const uint32_t _off = _row * (KV_STRIDE * 4) + _c4 * 4;              \
            cp_async16(_kd + _off, &K[_g]);                                      \
            cp_async16(_vd + _off, &V[_g]);                                      \
        }                                                                        \
        asm volatile("cp.async.commit_group;");                                  \
    } while (0)

    uint32_t qf[16][4];
    {
        const uint32_t* Qr0 = (const uint32_t*)&Q[(size_t)(tok0 + qt * 128 + warp * 16 + r0) * DM + h * DH];
        const uint32_t* Qr1 = (const uint32_t*)&Q[(size_t)(tok0 + qt * 128 + warp * 16 + r0 + 8) * DM + h * DH];
        #pragma unroll
        for (int kk = 0; kk < 16; kk++) {
            qf[kk][0] = Qr0[kk * 8 + c0];
            qf[kk][1] = Qr1[kk * 8 + c0];
            qf[kk][2] = Qr0[kk * 8 + c0 + 4];
            qf[kk][3] = Qr1[kk * 8 + c0 + 4];
        }
    }

    float m0 = -1e30f, m1 = -1e30f, l0 = 0.0f, l1 = 0.0f;
    float acc[16][4];
    #pragma unroll
    for (int j = 0; j < 16; j++)
        #pragma unroll
        for (int r = 0; r < 4; r++) acc[j][r] = 0.0f;

    const int ktmax = 2 * qt + 1;
    ATT_LOAD(0, 0);

    for (int kt = 0; kt <= ktmax; kt++) {
        const int cur = kt & 1;
        if (kt < ktmax) {
            ATT_LOAD(kt + 1, cur ^ 1);
            asm volatile("cp.async.wait_group 1;");
        } else {
            asm volatile("cp.async.wait_group 0;");
        }
        __syncthreads();

        const uint32_t* Ksb = smu + cur * KV_TILE_U;
        const uint32_t* Vsb = smu + (2 + cur) * KV_TILE_U;

        float s[8][4];
        #pragma unroll
        for (int j = 0; j < 8; j++)
            #pragma unroll
            for (int r = 0; r < 4; r++) s[j][r] = 0.0f;

        #pragma unroll
        for (int kk = 0; kk < 16; kk++) {
            const int kc = kk * 8 + c0;
            #pragma unroll
            for (int j = 0; j < 8; j++) {
                uint32_t bf[2];
                bf[0] = Ksb[(j * 8 + r0) * KV_STRIDE + kc];
                bf[1] = Ksb[(j * 8 + r0) * KV_STRIDE + kc + 4];
                mma_tf32(s[j], qf[kk], bf);
            }
        }

        if (kt >= 2 * qt) {
            const int grow0 = qt * 128 + warp * 16 + r0;
            #pragma unroll
            for (int j = 0; j < 8; j++) {
                const int gcol = kt * 64 + j * 8 + 2 * c0;
                if (gcol     > grow0)     s[j][0] = -1e30f;
                if (gcol + 1 > grow0)     s[j][1] = -1e30f;
                if (gcol     > grow0 + 8) s[j][2] = -1e30f;
                if (gcol + 1 > grow0 + 8) s[j][3] = -1e30f;
            }
        }

        float mx0 = -1e30f, mx1 = -1e30f;
        #pragma unroll
        for (int j = 0; j < 8; j++) {
            mx0 = fmaxf(mx0, fmaxf(s[j][0], s[j][1]));
            mx1 = fmaxf(mx1, fmaxf(s[j][2], s[j][3]));
        }
        mx0 = fmaxf(mx0, __shfl_xor_sync(0xffffffffu, mx0, 1));
        mx0 = fmaxf(mx0, __shfl_xor_sync(0xffffffffu, mx0, 2));
        mx1 = fmaxf(mx1, __shfl_xor_sync(0xffffffffu, mx1, 1));
        mx1 = fmaxf(mx1, __shfl_xor_sync(0xffffffffu, mx1, 2));

        const float mn0 = fmaxf(m0, mx0);
        const float mn1 = fmaxf(m1, mx1);
        const float corr0 = __expf(m0 - mn0);
        const float corr1 = __expf(m1 - mn1);
        float ls0 = 0.0f, ls1 = 0.0f;
        const int prow0 = warp * 16 + r0;
        #pragma unroll
        for (int j = 0; j < 8; j++) {
            float p0 = __expf(s[j][0] - mn0);
            float p1 = __expf(s[j][1] - mn0);
            float p2 = __expf(s[j][2] - mn1);
            float p3 = __expf(s[j][3] - mn1);
            ls0 += p0 + p1;
            ls1 += p2 + p3;
            Ps[prow0 * PS_STRIDE + j * 8 + 2 * c0]           = tf32_bits(p0);
            Ps[prow0 * PS_STRIDE + j * 8 + 2 * c0 + 1]       = tf32_bits(p1);
            Ps[(prow0 + 8) * PS_STRIDE + j * 8 + 2 * c0]     = tf32_bits(p2);
            Ps[(prow0 + 8) * PS_STRIDE + j * 8 + 2 * c0 + 1] = tf32_bits(p3);
        }
        ls0 += __shfl_xor_sync(0xffffffffu, ls0, 1);
        ls0 += __shfl_xor_sync(0xffffffffu, ls0, 2);
        ls1 += __shfl_xor_sync(0xffffffffu, ls1, 1);
        ls1 += __shfl_xor_sync(0xffffffffu, ls1, 2);
        l0 = l0 * corr0 + ls0;  m0 = mn0;
        l1 = l1 * corr1 + ls1;  m1 = mn1;

        #pragma unroll
        for (int j = 0; j < 16; j++) {
            acc[j][0] *= corr0; acc[j][1] *= corr0;
            acc[j][2] *= corr1; acc[j][3] *= corr1;
        }
        __syncwarp();

        #pragma unroll
        for (int kk = 0; kk < 8; kk++) {
            const int kc = kk * 8 + c0;
            uint32_t af[4];
            af[0] = Ps[prow0 * PS_STRIDE + kc];
            af[1] = Ps[(prow0 + 8) * PS_STRIDE + kc];
            af[2] = Ps[prow0 * PS_STRIDE + kc + 4];
            af[3] = Ps[(prow0 + 8) * PS_STRIDE + kc + 4];
            #pragma unroll
            for (int j = 0; j < 16; j++) {
                uint32_t bf[2];
                bf[0] = Vsb[kc * KV_STRIDE + j * 8 + r0];
                bf[1] = Vsb[(kc + 4) * KV_STRIDE + j * 8 + r0];
                mma_tf32(acc[j], af, bf);
            }
        }
        __syncthreads();
    }

    // epilogue: normalize, write fp16 plane
    const float inv0 = 1.0f / l0;
    const float inv1 = 1.0f / l1;
    const size_t row0 = (size_t)(tok0 + qt * 128 + warp * 16 + r0);
    #pragma unroll
    for (int j = 0; j < 16; j++) {
        const int col = h * DH + j * 8 + 2 * c0;
        *(uint32_t*)&Oh[row0 * DM + col]       = pack_h2(acc[j][0] * inv0, acc[j][1] * inv0);
        *(uint32_t*)&Oh[(row0 + 8) * DM + col] = pack_h2(acc[j][2] * inv1, acc[j][3] * inv1);
    }
}

// ---------------------------------------------------------------------------
extern "C" void kernel_launch(void* const* d_in, const int* in_sizes, int n_in,
                              void* d_out, int out_size)
{
    const float* x   = (const float*)d_in[0];
    const float* Wq  = (const float*)d_in[1];
    const float* Wk  = (const float*)d_in[2];
    const float* Wv  = (const float*)d_in[3];
    const float* Wo  = (const float*)d_in[4];
    const float* kvc = (const float*)d_in[5];
    const int*   bt  = (const int*)d_in[7];

    float* out   = (float*)d_out;
    float* cache = out + OUT_ELEMS;

    float *Qb, *Kb, *Vb;
    __half *xh, *AOh, *Wqh, *Wkh, *Wvh, *Woh;
    cudaGetSymbolAddress((void**)&Qb,  g_Q);
    cudaGetSymbolAddress((void**)&Kb,  g_K);
    cudaGetSymbolAddress((void**)&Vb,  g_V);
    cudaGetSymbolAddress((void**)&xh,  g_xh);
    cudaGetSymbolAddress((void**)&AOh, g_AOh);
    cudaGetSymbolAddress((void**)&Wqh, g_Wqh);
    cudaGetSymbolAddress((void**)&Wkh, g_Wkh);
    cudaGetSymbolAddress((void**)&Wvh, g_Wvh);
    cudaGetSymbolAddress((void**)&Woh, g_Woh);

    cudaFuncSetAttribute(gemm_fp16_multi, cudaFuncAttributeMaxDynamicSharedMemorySize, GEMM_SMEM);
    cudaFuncSetAttribute(flash_attn_mma, cudaFuncAttributeMaxDynamicSharedMemorySize, ATT_SMEM);

    pack_half<<<(TOK * DM / 4) / 256, 256>>>(x,  xh,  TOK * DM / 4);
    pack_half<<<(DM * DM / 4) / 256, 256>>>(Wq, Wqh, DM * DM / 4);
    pack_half<<<(DM * DM / 4) / 256, 256>>>(Wk, Wkh, DM * DM / 4);
    pack_half<<<(DM * DM / 4) / 256, 256>>>(Wv, Wvh, DM * DM / 4);
    pack_half<<<(DM * DM / 4) / 256, 256>>>(Wo, Woh, DM * DM / 4);

    gemm_fp16_multi<<<dim3(48, 64), 256, GEMM_SMEM>>>(
        xh, Wqh, Wkh, Wvh, Qb, Kb, Vb);

    cudaMemcpyAsync(cache, kvc, (size_t)CACHE_ELEMS * sizeof(float),
                    cudaMemcpyDeviceToDevice);

    rope_scatter<<<(TOK * NH * 64) / 256, 256>>>(Qb, Kb, Vb, bt, cache);

    flash_attn_mma<<<dim3(SEQ / 128, 8 * NH), 256, ATT_SMEM>>>(Qb, Kb, Vb, AOh);

    gemm_fp16_multi<<<dim3(16, 64), 256, GEMM_SMEM>>>(
        AOh, Woh, Woh, Woh, out, out, out);
}

// round 17
// speedup vs baseline: 4.7681x; 1.0780x over previous
#include <cuda_runtime.h>
#include <cuda_fp16.h>
#include <cuda_bf16.h>
#include <cstdint>

// Problem constants
#define TOK   8192
#define DM    2048
#define NH    16
#define DH    128
#define SEQ   1024
#define BSZ   256
#define NBLK  64
#define CACHE_ELEMS (NBLK*2*NH*BSZ*DH)  // 33554432
#define OUT_ELEMS   (TOK*DM)            // 16777216

// Scratch
__device__ float g_Q [TOK*DM];           // fp32 GEMM outputs
__device__ float g_K [TOK*DM];
__device__ float g_V [TOK*DM];
__device__ __half g_Qh[TOK*DM];          // fp16 attention operands (Q pre-scaled)
__device__ __half g_Kh[TOK*DM];
__device__ __half g_Vt[TOK*DM];          // V transposed: [b][h][dh][seq]
__device__ __half g_xh [TOK*DM];
__device__ __half g_AOh[TOK*DM];
__device__ __half g_Wqh[DM*DM];
__device__ __half g_Wkh[DM*DM];
__device__ __half g_Wvh[DM*DM];
__device__ __half g_Woh[DM*DM];

__device__ __forceinline__ uint32_t smem_u32(const void* p) {
    uint32_t a;
    asm("{ .reg .u64 t; cvta.to.shared.u64 t, %1; cvt.u32.u64 %0, t; }" : "=r"(a) : "l"(p));
    return a;
}
__device__ __forceinline__ void cp_async16(uint32_t dst, const void* src) {
    asm volatile("cp.async.ca.shared.global [%0], [%1], 16;" :: "r"(dst), "l"(src));
}
// fp16 m16n8k16 — fragment layout (thread = r0*4+c0):
//   a0=(r0, k=2c0|2c0+1) a1=(r0+8, same) a2=(r0, k+8) a3=(r0+8, k+8)
//   b0=(n=r0, k=2c0|2c0+1) b1=(n=r0, k+8)
//   d0=(r0,2c0) d1=(r0,2c0+1) d2=(r0+8,2c0) d3=(r0+8,2c0+1)
__device__ __forceinline__ void mma_fp16(float* d, const uint32_t* a, const uint32_t* b) {
    asm volatile(
        "mma.sync.aligned.m16n8k16.row.col.f32.f16.f16.f32 "
        "{%0,%1,%2,%3}, {%4,%5,%6,%7}, {%8,%9}, {%0,%1,%2,%3};"
        : "+f"(d[0]), "+f"(d[1]), "+f"(d[2]), "+f"(d[3])
        : "r"(a[0]), "r"(a[1]), "r"(a[2]), "r"(a[3]), "r"(b[0]), "r"(b[1]));
}
__device__ __forceinline__ uint32_t pack_h2(float x, float y) {
    __half hx = __float2half_rn(x);
    __half hy = __float2half_rn(y);
    return (uint32_t)__half_as_ushort(hx) | ((uint32_t)__half_as_ushort(hy) << 16);
}

// ---------------------------------------------------------------------------
// Pack fp32 -> fp16 plane. 4 elems/thread.
// ---------------------------------------------------------------------------
__global__ void __launch_bounds__(256) pack_half(const float* __restrict__ s,
                                                 __half* __restrict__ h,
                                                 int n4)
{
    int i = blockIdx.x * 256 + threadIdx.x;
    if (i >= n4) return;
    float4 v = ((const float4*)s)[i];
    *(uint2*)&h[4 * (size_t)i] = make_uint2(pack_h2(v.x, v.y), pack_h2(v.z, v.w));
}

// ---------------------------------------------------------------------------
// fp16 single-pass GEMM (R16-verified): C[M,N] = A[M,K] * B[N,K]^T.
// ---------------------------------------------------------------------------
#define GK 2048
#define BBK 32
#define GNSTEP (GK / BBK)
#define PLANE_B 10240
#define STAGE_B (2 * PLANE_B)
#define GEMM_SMEM (2 * STAGE_B)

__global__ void __launch_bounds__(256, 1) gemm_fp16_multi(
    const __half* __restrict__ Ah,
    const __half* __restrict__ B0, const __half* __restrict__ B1, const __half* __restrict__ B2,
    float* __restrict__ C0, float* __restrict__ C1, float* __restrict__ C2)
{
    extern __shared__ uint32_t smu[];
    const uint32_t sbase = smem_u32(smu);

    const int sel = blockIdx.x >> 4;
    const __half* B = (sel == 0) ? B0 : (sel == 1) ? B1 : B2;
    float*        C = (sel == 0) ? C0 : (sel == 1) ? C1 : C2;

    const int tid  = threadIdx.x;
    const int lane = tid & 31;
    const int wid  = tid >> 5;
    const int wm   = wid & 1;
    const int wn   = wid >> 1;
    const int bm   = blockIdx.y * 128;
    const int bn   = (blockIdx.x & 15) * 128;
    const int r0   = lane >> 2;
    const int c0   = lane & 3;

    const int ldrow = tid >> 2;
    const int ldch  = tid & 3;
    const __half* A_t = Ah + (size_t)(bm + ldrow) * GK + ldch * 8;
    const __half* B_t = B  + (size_t)(bn + ldrow) * GK + ldch * 8;
    const uint32_t sdst = sbase + ldrow * 80 + ldch * 16;

    #define LOAD_TILES(KIDX, BUF) do {                                           \
        const int _k0 = (KIDX) * BBK;                                            \
        const uint32_t _d = sdst + (BUF) * STAGE_B;                              \
        _Pragma("unroll")                                                        \
        for (int _i = 0; _i < 2; _i++) {                                         \
            const size_t _g = (size_t)_i * 64 * GK + _k0;                        \
            const uint32_t _o = _i * 64 * 80;                                    \
            cp_async16(_d + _o,           A_t + _g);                             \
            cp_async16(_d + _o + PLANE_B, B_t + _g);                             \
        }                                                                        \
        asm volatile("cp.async.commit_group;");                                  \
    } while (0)

    float acc[4][4][4];
    #pragma unroll
    for (int mi = 0; mi < 4; mi++)
        #pragma unroll
        for (int nj = 0; nj < 4; nj++)
            #pragma unroll
            for (int r = 0; r < 4; r++) acc[mi][nj][r] = 0.0f;

    LOAD_TILES(0, 0);

    for (int s = 0; s < GNSTEP; s++) {
        const int buf = s & 1;
        if (s + 1 < GNSTEP) {
            LOAD_TILES(s + 1, buf ^ 1);
            asm volatile("cp.async.wait_group 1;");
        } else {
            asm volatile("cp.async.wait_group 0;");
        }
        __syncthreads();

        const uint32_t* P  = smu + buf * (STAGE_B / 4);
        const uint32_t* PA = P;
        const uint32_t* PB = P + PLANE_B / 4;

        #pragma unroll
        for (int kk = 0; kk < 2; kk++) {
            uint32_t af[4][4], bf[4][2];
            #pragma unroll
            for (int mi = 0; mi < 4; mi++) {
                const int idx = (wm * 64 + mi * 16 + r0) * 20 + kk * 8 + c0;
                af[mi][0] = PA[idx];       af[mi][1] = PA[idx + 160];
                af[mi][2] = PA[idx + 4];   af[mi][3] = PA[idx + 164];
            }
            #pragma unroll
            for (int nj = 0; nj < 4; nj++) {
                const int nidx = (wn * 32 + nj * 8 + r0) * 20 + kk * 8 + c0;
                bf[nj][0] = PB[nidx];      bf[nj][1] = PB[nidx + 4];
            }
            #pragma unroll
            for (int mi = 0; mi < 4; mi++)
                #pragma unroll
                for (int nj = 0; nj < 4; nj++)
                    mma_fp16(acc[mi][nj], af[mi], bf[nj]);
        }
        __syncthreads();
    }

    #pragma unroll
    for (int mi = 0; mi < 4; mi++) {
        const int grow = bm + wm * 64 + mi * 16 + r0;
        #pragma unroll
        for (int nj = 0; nj < 4; nj++) {
            const int gcol = bn + wn * 32 + nj * 8 + c0 * 2;
            *(float2*)&C[(size_t)grow * DM + gcol]       = make_float2(acc[mi][nj][0], acc[mi][nj][1]);
            *(float2*)&C[(size_t)(grow + 8) * DM + gcol] = make_float2(acc[mi][nj][2], acc[mi][nj][3]);
        }
    }
}

// ---------------------------------------------------------------------------
// RoPE + paged-KV scatter. Exact fp32 cache write; emits fp16 Qh (scaled),
// Kh, and transposed Vt for attention.
// ---------------------------------------------------------------------------
__global__ void __launch_bounds__(256) rope_scatter(const float* __restrict__ Q,
                                                    const float* __restrict__ K,
                                                    const float* __restrict__ V,
                                                    const int* __restrict__ block_table,
                                                    float* __restrict__ cache,
                                                    __half* __restrict__ Qh,
                                                    __half* __restrict__ Kh,
                                                    __half* __restrict__ Vt)
{
    int idx = blockIdx.x * blockDim.x + threadIdx.x;
    int i = idx & 63;
    int h = (idx >> 6) & (NH - 1);
    int t = idx >> 10;
    if (t >= TOK) return;

    const float scale = 0.08838834764831845f; // 1/sqrt(128)
    int pos = t & (SEQ - 1);
    float inv_freq = __powf(10000.0f, -(float)(2 * i) / 128.0f);
    float ang = (float)pos * inv_freq;
    float s, c;
    __sincosf(ang, &s, &c);

    size_t base = (size_t)t * DM + h * DH + i;
    float q1 = Q[base], q2 = Q[base + 64];
    float q1r = q1 * c - q2 * s;
    float q2r = q2 * c + q1 * s;

    float k1 = K[base], k2 = K[base + 64];
    float k1r = k1 * c - k2 * s;
    float k2r = k2 * c + k1 * s;

    float v1 = V[base], v2 = V[base + 64];

    int seq = t >> 10;
    // exact cache write
    int logical = (t & (SEQ - 1)) >> 8;
    int phys    = block_table[seq * (SEQ / BSZ) + logical];
    int off     = t & (BSZ - 1);
    size_t kbase = (size_t)phys * (2 * NH * BSZ * DH) + (size_t)h * (BSZ * DH)
                 + (size_t)off * DH + i;
    cache[kbase]      = k1r;
    cache[kbase + 64] = k2r;
    size_t vbase = kbase + (size_t)NH * BSZ * DH;
    cache[vbase]      = v1;
    cache[vbase + 64] = v2;

    // fp16 attention operands
    Qh[base]      = __float2half_rn(q1r * scale);
    Qh[base + 64] = __float2half_rn(q2r * scale);
    Kh[base]      = __float2half_rn(k1r);
    Kh[base + 64] = __float2half_rn(k2r);
    // V transposed: Vt[((seq*NH + h)*DH + d)*SEQ + pos]
    size_t vt = ((size_t)(seq * NH + h) * DH + i) * SEQ + pos;
    Vt[vt]            = __float2half_rn(v1);
    Vt[vt + 64 * SEQ] = __float2half_rn(v2);
}

// ---------------------------------------------------------------------------
// Flash attention, fp16 m16n8k16, cp.async double-buffered K/Vt, Q in regs.
// BM=128 queries/CTA (8 warps x 16 rows), BN=64 keys/tile.
// smem (u32 idx): K0[64x68] K1 V0[128x36] V1 Ps[128x36]
// ---------------------------------------------------------------------------
#define KS_STR 68
#define VT_STR 36
#define PS_STR 36
#define K_TILE_U (64 * KS_STR)    // 4352
#define V_TILE_U (128 * VT_STR)   // 4608
#define OFF_K0 0
#define OFF_K1 K_TILE_U
#define OFF_V0 (2 * K_TILE_U)
#define OFF_V1 (2 * K_TILE_U + V_TILE_U)
#define OFF_PS (2 * K_TILE_U + 2 * V_TILE_U)
#define ATT_SMEM ((OFF_PS + 128 * PS_STR) * 4)   // 90112 bytes

__global__ void __launch_bounds__(256, 1) flash_attn_mma(const __half* __restrict__ Qh,
                                                         const __half* __restrict__ Kh,
                                                         const __half* __restrict__ Vt,
                                                         __half* __restrict__ Oh)
{
    extern __shared__ uint32_t smu[];
    const uint32_t sbase = smem_u32(smu);
    uint32_t* Ps = smu + OFF_PS;

    const int qt   = blockIdx.x;
    const int bh   = blockIdx.y;
    const int b    = bh >> 4;
    const int h    = bh & 15;
    const int tid  = threadIdx.x;
    const int warp = tid >> 5;
    const int lane = tid & 31;
    const int r0   = lane >> 2;
    const int c0   = lane & 3;
    const int tok0 = b * SEQ;
    const __half* VtBase = Vt + (size_t)(b * NH + h) * DH * SEQ;

    // K tile: 64 rows x 256B (16 chunks); V tile: 128 rows x 128B (8 chunks)
    #define ATT_LOAD(KT, STG) do {                                               \
        const uint32_t _kd = sbase + ((STG) ? OFF_K1 : OFF_K0) * 4;              \
        const uint32_t _vd = sbase + ((STG) ? OFF_V1 : OFF_V0) * 4;              \
        _Pragma("unroll")                                                        \
        for (int _i = 0; _i < 4; _i++) {                                         \
            const int _idx = tid + _i * 256;                                     \
            const int _kr  = _idx >> 4;                                          \
            const int _kc  = _idx & 15;                                          \
            cp_async16(_kd + _kr * (KS_STR * 4) + _kc * 16,                      \
                       &Kh[(size_t)(tok0 + (KT) * 64 + _kr) * DM + h * DH + _kc * 8]); \
            const int _vr  = _idx >> 3;                                          \
            const int _vc  = _idx & 7;                                           \
            cp_async16(_vd + _vr * (VT_STR * 4) + _vc * 16,                      \
                       &VtBase[(size_t)_vr * SEQ + (KT) * 64 + _vc * 8]);        \
        }                                                                        \
        asm volatile("cp.async.commit_group;");                                  \
    } while (0)

    // Q fragments in registers: 8 k16-steps, 4 u32 each
    uint32_t qf[8][4];
    {
        const uint32_t* Qr0 = (const uint32_t*)&Qh[(size_t)(tok0 + qt * 128 + warp * 16 + r0) * DM + h * DH];
        const uint32_t* Qr1 = (const uint32_t*)&Qh[(size_t)(tok0 + qt * 128 + warp * 16 + r0 + 8) * DM + h * DH];
        #pragma unroll
        for (int kk = 0; kk < 8; kk++) {
            qf[kk][0] = Qr0[kk * 8 + c0];
            qf[kk][1] = Qr1[kk * 8 + c0];
            qf[kk][2] = Qr0[kk * 8 + c0 + 4];
            qf[kk][3] = Qr1[kk * 8 + c0 + 4];
        }
    }

    float m0 = -1e30f, m1 = -1e30f, l0 = 0.0f, l1 = 0.0f;
    float acc[16][4];
    #pragma unroll
    for (int j = 0; j < 16; j++)
        #pragma unroll
        for (int r = 0; r < 4; r++) acc[j][r] = 0.0f;

    const int ktmax = 2 * qt + 1;
    ATT_LOAD(0, 0);

    for (int kt = 0; kt <= ktmax; kt++) {
        const int cur = kt & 1;
        if (kt < ktmax) {
            ATT_LOAD(kt + 1, cur ^ 1);
            asm volatile("cp.async.wait_group 1;");
        } else {
            asm volatile("cp.async.wait_group 0;");
        }
        __syncthreads();

        const uint32_t* Ksb = smu + (cur ? OFF_K1 : OFF_K0);
        const uint32_t* Vsb = smu + (cur ? OFF_V1 : OFF_V0);

        // S = Q K^T : 8 ksteps x 8 n-tiles
        float s[8][4];
        #pragma unroll
        for (int j = 0; j < 8; j++)
            #pragma unroll
            for (int r = 0; r < 4; r++) s[j][r] = 0.0f;

        #pragma unroll
        for (int kk = 0; kk < 8; kk++) {
            #pragma unroll
            for (int j = 0; j < 8; j++) {
                uint32_t bf[2];
                bf[0] = Ksb[(j * 8 + r0) * KS_STR + kk * 8 + c0];
                bf[1] = Ksb[(j * 8 + r0) * KS_STR + kk * 8 + c0 + 4];
                mma_fp16(s[j], qf[kk], bf);
            }
        }

        if (kt >= 2 * qt) {
            const int grow0 = qt * 128 + warp * 16 + r0;
            #pragma unroll
            for (int j = 0; j < 8; j++) {
                const int gcol = kt * 64 + j * 8 + 2 * c0;
                if (gcol     > grow0)     s[j][0] = -1e30f;
                if (gcol + 1 > grow0)     s[j][1] = -1e30f;
                if (gcol     > grow0 + 8) s[j][2] = -1e30f;
                if (gcol + 1 > grow0 + 8) s[j][3] = -1e30f;
            }
        }

        // warp-private online softmax
        float mx0 = -1e30f, mx1 = -1e30f;
        #pragma unroll
        for (int j = 0; j < 8; j++) {
            mx0 = fmaxf(mx0, fmaxf(s[j][0], s[j][1]));
            mx1 = fmaxf(mx1, fmaxf(s[j][2], s[j][3]));
        }
        mx0 = fmaxf(mx0, __shfl_xor_sync(0xffffffffu, mx0, 1));
        mx0 = fmaxf(mx0, __shfl_xor_sync(0xffffffffu, mx0, 2));
        mx1 = fmaxf(mx1, __shfl_xor_sync(0xffffffffu, mx1, 1));
        mx1 = fmaxf(mx1, __shfl_xor_sync(0xffffffffu, mx1, 2));

        const float mn0 = fmaxf(m0, mx0);
        const float mn1 = fmaxf(m1, mx1);
        const float corr0 = __expf(m0 - mn0);
        const float corr1 = __expf(m1 - mn1);
        float ls0 = 0.0f, ls1 = 0.0f;
        const int prow0 = warp * 16 + r0;
        #pragma unroll
        for (int j = 0; j < 8; j++) {
            float p0 = __expf(s[j][0] - mn0);
            float p1 = __expf(s[j][1] - mn0);
            float p2 = __expf(s[j][2] - mn1);
            float p3 = __expf(s[j][3] - mn1);
            ls0 += p0 + p1;
            ls1 += p2 + p3;
            Ps[prow0 * PS_STR + j * 4 + c0]       = pack_h2(p0, p1);
            Ps[(prow0 + 8) * PS_STR + j * 4 + c0] = pack_h2(p2, p3);
        }
        ls0 += __shfl_xor_sync(0xffffffffu, ls0, 1);
        ls0 += __shfl_xor_sync(0xffffffffu, ls0, 2);
        ls1 += __shfl_xor_sync(0xffffffffu, ls1, 1);
        ls1 += __shfl_xor_sync(0xffffffffu, ls1, 2);
        l0 = l0 * corr0 + ls0;  m0 = mn0;
        l1 = l1 * corr1 + ls1;  m1 = mn1;

        #pragma unroll
        for (int j = 0; j < 16; j++) {
            acc[j][0] *= corr0; acc[j][1] *= corr0;
            acc[j][2] *= corr1; acc[j][3] *= corr1;
        }
        __syncwarp();

        // O += P V : 4 k16-steps over 64 keys, 16 dh-tiles
        #pragma unroll
        for (int kk = 0; kk < 4; kk++) {
            uint32_t af[4];
            af[0] = Ps[prow0 * PS_STR + kk * 8 + c0];
            af[1] = Ps[(prow0 + 8) * PS_STR + kk * 8 + c0];
            af[2] = Ps[prow0 * PS_STR + kk * 8 + c0 + 4];
            af[3] = Ps[(prow0 + 8) * PS_STR + kk * 8 + c0 + 4];
            #pragma unroll
            for (int j = 0; j < 16; j++) {
                uint32_t bf[2];
                bf[0] = Vsb[(j * 8 + r0) * VT_STR + kk * 8 + c0];
                bf[1] = Vsb[(j * 8 + r0) * VT_STR + kk * 8 + c0 + 4];
                mma_fp16(acc[j], af, bf);
            }
        }
        __syncthreads();
    }

    // epilogue: normalize, write fp16 plane
    const float inv0 = 1.0f / l0;
    const float inv1 = 1.0f / l1;
    const size_t row0 = (size_t)(tok0 + qt * 128 + warp * 16 + r0);
    #pragma unroll
    for (int j = 0; j < 16; j++) {
        const int col = h * DH + j * 8 + 2 * c0;
        *(uint32_t*)&Oh[row0 * DM + col]       = pack_h2(acc[j][0] * inv0, acc[j][1] * inv0);
        *(uint32_t*)&Oh[(row0 + 8) * DM + col] = pack_h2(acc[j][2] * inv1, acc[j][3] * inv1);
    }
}

// ---------------------------------------------------------------------------
extern "C" void kernel_launch(void* const* d_in, const int* in_sizes, int n_in,
                              void* d_out, int out_size)
{
    const float* x   = (const float*)d_in[0];
    const float* Wq  = (const float*)d_in[1];
    const float* Wk  = (const float*)d_in[2];
    const float* Wv  = (const float*)d_in[3];
    const float* Wo  = (const float*)d_in[4];
    const float* kvc = (const float*)d_in[5];
    const int*   bt  = (const int*)d_in[7];

    float* out   = (float*)d_out;
    float* cache = out + OUT_ELEMS;

    float *Qb, *Kb, *Vb;
    __half *Qh, *Kh, *Vt, *xh, *AOh, *Wqh, *Wkh, *Wvh, *Woh;
    cudaGetSymbolAddress((void**)&Qb,  g_Q);
    cudaGetSymbolAddress((void**)&Kb,  g_K);
    cudaGetSymbolAddress((void**)&Vb,  g_V);
    cudaGetSymbolAddress((void**)&Qh,  g_Qh);
    cudaGetSymbolAddress((void**)&Kh,  g_Kh);
    cudaGetSymbolAddress((void**)&Vt,  g_Vt);
    cudaGetSymbolAddress((void**)&xh,  g_xh);
    cudaGetSymbolAddress((void**)&AOh, g_AOh);
    cudaGetSymbolAddress((void**)&Wqh, g_Wqh);
    cudaGetSymbolAddress((void**)&Wkh, g_Wkh);
    cudaGetSymbolAddress((void**)&Wvh, g_Wvh);
    cudaGetSymbolAddress((void**)&Woh, g_Woh);

    cudaFuncSetAttribute(gemm_fp16_multi, cudaFuncAttributeMaxDynamicSharedMemorySize, GEMM_SMEM);
    cudaFuncSetAttribute(flash_attn_mma, cudaFuncAttributeMaxDynamicSharedMemorySize, ATT_SMEM);

    pack_half<<<(TOK * DM / 4) / 256, 256>>>(x,  xh,  TOK * DM / 4);
    pack_half<<<(DM * DM / 4) / 256, 256>>>(Wq, Wqh, DM * DM / 4);
    pack_half<<<(DM * DM / 4) / 256, 256>>>(Wk, Wkh, DM * DM / 4);
    pack_half<<<(DM * DM / 4) / 256, 256>>>(Wv, Wvh, DM * DM / 4);
    pack_half<<<(DM * DM / 4) / 256, 256>>>(Wo, Woh, DM * DM / 4);

    gemm_fp16_multi<<<dim3(48, 64), 256, GEMM_SMEM>>>(
        xh, Wqh, Wkh, Wvh, Qb, Kb, Vb);

    cudaMemcpyAsync(cache, kvc, (size_t)CACHE_ELEMS * sizeof(float),
                    cudaMemcpyDeviceToDevice);

    rope_scatter<<<(TOK * NH * 64) / 256, 256>>>(Qb, Kb, Vb, bt, cache, Qh, Kh, Vt);

    flash_attn_mma<<<dim3(SEQ / 128, 8 * NH), 256, ATT_SMEM>>>(Qh, Kh, Vt, AOh);

    gemm_fp16_multi<<<dim3(16, 64), 256, GEMM_SMEM>>>(
        AOh, Woh, Woh, Woh, out, out, out);
}